// round 7
// baseline (speedup 1.0000x reference)
#include <cuda_runtime.h>

#define NN 50000
#define NE 200000
#define H  128
#define HV4 32   // H/4

// Scratch (device globals: allocation-free per harness rules)
__device__ float g_node_h[NN * H];        // 25.6 MB
__device__ float g_agg[NN * H];           // 25.6 MB  per-layer atomic accumulator
__device__ float g_agg_base[NN * H];      // 25.6 MB  Σ edge_h per dst (factorized)
__device__ float g_escratch[NN * 65];     // precompute: eaggF [NN,64] + deg [NN]; layers: sdot2 [NN]
__device__ float g_edot[NE];              // folded edge-constant gate logit
__device__ float g_wcombo[65];            // W_edge @ w_top_e (64) + folded bias

__device__ __forceinline__ void fma4(float4& acc, const float4& wv, float s) {
    acc.x += wv.x * s;
    acc.y += wv.y * s;
    acc.z += wv.z * s;
    acc.w += wv.w * s;
}
__device__ __forceinline__ void ffma2(unsigned long long& d,
                                      unsigned long long a,
                                      unsigned long long b) {
    asm("fma.rn.f32x2 %0, %1, %2, %0;" : "+l"(d) : "l"(a), "l"(b));
}
__device__ __forceinline__ float ull_lo(unsigned long long u) {
    return __uint_as_float((unsigned)(u & 0xffffffffu));
}
__device__ __forceinline__ float ull_hi(unsigned long long u) {
    return __uint_as_float((unsigned)(u >> 32));
}
__device__ __forceinline__ void red_v4(float* p, float a, float b, float c, float d) {
    asm volatile("red.global.add.v4.f32 [%0], {%1,%2,%3,%4};"
                 :: "l"(p), "f"(a), "f"(b), "f"(c), "f"(d) : "memory");
}
__device__ __forceinline__ void red_v2(float* p, float a, float b) {
    asm volatile("red.global.add.v2.f32 [%0], {%1,%2};"
                 :: "l"(p), "f"(a), "f"(b) : "memory");
}

__global__ void zero_kernel(float4* __restrict__ p, int n4) {
    int i = blockIdx.x * blockDim.x + threadIdx.x;
    if (i < n4) p[i] = make_float4(0.f, 0.f, 0.f, 0.f);
}

// ---------------------------------------------------------------------------
// wcombo[k] = sum_h W_edge[k,h] * W_top[2H+h];  wcombo[64] = folded bias
// ---------------------------------------------------------------------------
__global__ void combo_kernel(const float* __restrict__ W_edge,
                             const float* __restrict__ W_top,
                             const float* __restrict__ b_edge,
                             const float* __restrict__ b_top,
                             float* __restrict__ wcombo)
{
    const int k = threadIdx.x;   // 64 threads
    float s = 0.f;
    for (int h = 0; h < H; h++) s += W_edge[k * H + h] * W_top[2 * H + h];
    wcombo[k] = s;
    if (k == 0) {
        float b = b_top[0];
        for (int h = 0; h < H; h++) b += b_edge[h] * W_top[2 * H + h];
        wcombo[64] = b;
    }
}

// ---------------------------------------------------------------------------
// Per-edge precompute (once): edot[e] = ef[e].wcombo + bias_const; scatter raw
// edge_features into eaggF[dst] (red.v2), deg[dst] += 1.
// ---------------------------------------------------------------------------
__global__ void edge_pre_kernel(const float* __restrict__ ef,
                                const int* __restrict__ dst,
                                const float* __restrict__ wcombo,
                                float* __restrict__ eaggF,
                                float* __restrict__ deg,
                                float* __restrict__ edot)
{
    __shared__ float wsh[65];
    const int tid  = threadIdx.x;
    const int lane = tid & 31;
    const int wid  = tid >> 5;
    if (tid < 65) wsh[tid] = wcombo[tid];
    __syncthreads();

    const int e = blockIdx.x * 8 + wid;
    const int d = dst[e];
    float2 v = ((const float2*)ef)[(size_t)e * 32 + lane];
    float p = v.x * wsh[lane * 2] + v.y * wsh[lane * 2 + 1];
    #pragma unroll
    for (int off = 16; off; off >>= 1)
        p += __shfl_xor_sync(0xffffffffu, p, off);
    if (lane == 0) {
        edot[e] = p + wsh[64];
        atomicAdd(deg + d, 1.f);
    }
    red_v2(eaggF + (size_t)d * 64 + lane * 2, v.x, v.y);
}

// ---------------------------------------------------------------------------
// Embed GEMM (R3-proven formulation): out[rows,H] = X[rows,K] @ W[K,H] + scale*b
// 256 threads, 32-row chunks, 4 rows/warp, 4 cols/lane. W + X staged in smem.
// ---------------------------------------------------------------------------
template<int K, bool DEGBIAS, bool SDOT>
__global__ void embed_kernel(const float* __restrict__ X,
                             const float* __restrict__ W,
                             const float* __restrict__ b,
                             const float* __restrict__ deg,
                             const float* __restrict__ W_top,
                             float* __restrict__ out,
                             float2* __restrict__ sdot2, int rows)
{
    extern __shared__ float sm[];
    float* Wsh  = sm;            // K*H floats
    float* xbuf = sm + K * H;    // 32*K floats

    const int tid  = threadIdx.x;
    const int lane = tid & 31;
    const int wid  = tid >> 5;

    for (int i = tid; i < K * H / 4; i += 256)
        ((float4*)Wsh)[i] = ((const float4*)W)[i];
    const float4 bias = ((const float4*)b)[lane];
    float4 wsA, wdA;
    if (SDOT) {
        wsA = ((const float4*)W_top)[lane];
        wdA = ((const float4*)W_top)[32 + lane];
    }

    for (int r0 = blockIdx.x * 32; r0 < rows; r0 += gridDim.x * 32) {
        __syncthreads();
        const int nrows = min(32, rows - r0);
        for (int i = tid; i < nrows * (K / 4); i += 256)
            ((float4*)xbuf)[i] = ((const float4*)(X + (size_t)r0 * K))[i];
        __syncthreads();

        const int rbase = wid * 4;
        if (rbase < nrows) {
            float4 acc0 = make_float4(0.f, 0.f, 0.f, 0.f);
            float4 acc1 = acc0, acc2 = acc0, acc3 = acc0;
            const float* xr0 = xbuf + (rbase + 0) * K;
            const float* xr1 = xbuf + (rbase + 1) * K;
            const float* xr2 = xbuf + (rbase + 2) * K;
            const float* xr3 = xbuf + (rbase + 3) * K;
            #pragma unroll 4
            for (int k = 0; k < K; k++) {
                float4 wv = ((float4*)Wsh)[k * HV4 + lane];
                fma4(acc0, wv, xr0[k]);
                fma4(acc1, wv, xr1[k]);
                fma4(acc2, wv, xr2[k]);
                fma4(acc3, wv, xr3[k]);
            }
            float4 accs[4] = {acc0, acc1, acc2, acc3};
            #pragma unroll
            for (int rr = 0; rr < 4; rr++) {
                const float scb = DEGBIAS ? deg[r0 + rbase + rr] : 1.f;
                float4 o;
                o.x = accs[rr].x + scb * bias.x;
                o.y = accs[rr].y + scb * bias.y;
                o.z = accs[rr].z + scb * bias.z;
                o.w = accs[rr].w + scb * bias.w;
                ((float4*)out)[(size_t)(r0 + rbase + rr) * HV4 + lane] = o;
                if (SDOT) {
                    float s1 = o.x * wsA.x + o.y * wsA.y + o.z * wsA.z + o.w * wsA.w;
                    float s2 = o.x * wdA.x + o.y * wdA.y + o.z * wdA.z + o.w * wdA.w;
                    #pragma unroll
                    for (int off = 16; off; off >>= 1) {
                        s1 += __shfl_xor_sync(0xffffffffu, s1, off);
                        s2 += __shfl_xor_sync(0xffffffffu, s2, off);
                    }
                    if (lane == 0) sdot2[r0 + rbase + rr] = make_float2(s1, s2);
                }
            }
        }
    }
}

// ---------------------------------------------------------------------------
// Slim per-layer edge kernel: w = sigmoid(sdot2[s].x + sdot2[d].y + edot[e]);
// RED src_f * w into agg (pre-zeroed). One warp per edge, red.v4 per lane.
// ---------------------------------------------------------------------------
template<bool WRITE_EW>
__global__ void edge_slim_kernel(const float* __restrict__ node_h,
                                 const int* __restrict__ src,
                                 const int* __restrict__ dst,
                                 const float2* __restrict__ sdot2,
                                 const float* __restrict__ edot,
                                 float* __restrict__ agg,
                                 float* __restrict__ ew)
{
    const int tid  = threadIdx.x;
    const int lane = tid & 31;
    const int wid  = tid >> 5;
    const int e = blockIdx.x * 8 + wid;

    const int s = src[e];
    const int d = dst[e];
    const float2 ss = sdot2[s];
    const float2 dd = sdot2[d];
    const float p = ss.x + dd.y + edot[e];
    const float w = 1.f / (1.f + __expf(-p));

    float4 sf = ((const float4*)node_h)[(size_t)s * HV4 + lane];
    red_v4(agg + (size_t)d * H + lane * 4, sf.x * w, sf.y * w, sf.z * w, sf.w * w);

    if (WRITE_EW && lane == 0) ew[e] = w;
}

// ---------------------------------------------------------------------------
// GNN dense (FFMA2) + residual + LayerNorm + ReLU + sdot epilogue.
// updated = [node_h | agg+agg_base] @ W[256,128] + b.
// 512 threads (16 warps/SM), 32-row chunks, 2 rows/warp, 4 cols/lane.
// x staged PRE-DUPLICATED ({x,x} b64) so inner loop = LDS.128 + FFMA2 only.
// Clears agg in-place for the next layer.
// ---------------------------------------------------------------------------
template<bool LAST>
__global__ void gnn_kernel(const float* __restrict__ node_h,
                           float* __restrict__ agg,
                           const float* __restrict__ agg_base,
                           const float* __restrict__ W,     // [256,128]
                           const float* __restrict__ b,
                           const float* __restrict__ lns,
                           const float* __restrict__ lnb,
                           const float* __restrict__ W_top,
                           float* __restrict__ out,
                           float2* __restrict__ sdot2, int rows)
{
    extern __shared__ float sm[];
    float* Wsh = sm;                                           // 256*128 = 128 KB
    unsigned long long* xdup = (unsigned long long*)(sm + 256 * H);  // [32][256] ull = 64 KB

    const int tid  = threadIdx.x;
    const int lane = tid & 31;
    const int wid  = tid >> 5;

    for (int i = tid; i < 256 * H / 4; i += 512)
        ((float4*)Wsh)[i] = ((const float4*)W)[i];
    const float4 bias = ((const float4*)b)[lane];
    const float4 sc   = ((const float4*)lns)[lane];
    const float4 bi   = ((const float4*)lnb)[lane];
    const float4 wsA  = ((const float4*)W_top)[lane];
    const float4 wdA  = ((const float4*)W_top)[32 + lane];

    for (int r0 = blockIdx.x * 32; r0 < rows; r0 += gridDim.x * 32) {
        __syncthreads();
        const int nrows = min(32, rows - r0);
        // stage [node_h | agg+agg_base] duplicated: xdup[r][0:128]=node, [128:256]=agg
        for (int i = tid; i < nrows * HV4; i += 512) {
            const int r = i >> 5, c = i & 31;
            float4 v = ((const float4*)node_h)[(size_t)(r0 + r) * HV4 + c];
            float2* dn = (float2*)(xdup + (size_t)r * 256 + c * 4);
            dn[0] = make_float2(v.x, v.x);
            dn[1] = make_float2(v.y, v.y);
            dn[2] = make_float2(v.z, v.z);
            dn[3] = make_float2(v.w, v.w);
            float4 a  = ((const float4*)agg)[(size_t)(r0 + r) * HV4 + c];
            float4 ab = ((const float4*)agg_base)[(size_t)(r0 + r) * HV4 + c];
            a.x += ab.x; a.y += ab.y; a.z += ab.z; a.w += ab.w;
            float2* da = (float2*)(xdup + (size_t)r * 256 + H + c * 4);
            da[0] = make_float2(a.x, a.x);
            da[1] = make_float2(a.y, a.y);
            da[2] = make_float2(a.z, a.z);
            da[3] = make_float2(a.w, a.w);
            if (!LAST)
                ((float4*)agg)[(size_t)(r0 + r) * HV4 + c] = make_float4(0.f, 0.f, 0.f, 0.f);
        }
        __syncthreads();

        const int rbase = wid * 2;
        if (rbase < nrows) {   // nrows is 32 or 16, always even
            unsigned long long a00 = 0ull, a01 = 0ull, a10 = 0ull, a11 = 0ull;
            const unsigned long long* x0 = xdup + (size_t)(rbase + 0) * 256;
            const unsigned long long* x1 = xdup + (size_t)(rbase + 1) * 256;
            #pragma unroll 4
            for (int k = 0; k < 256; k++) {
                ulonglong2 wv = ((const ulonglong2*)(Wsh + (size_t)k * H))[lane];
                unsigned long long xx0 = x0[k];
                unsigned long long xx1 = x1[k];
                ffma2(a00, wv.x, xx0);
                ffma2(a01, wv.y, xx0);
                ffma2(a10, wv.x, xx1);
                ffma2(a11, wv.y, xx1);
            }
            unsigned long long accs[2][2] = {{a00, a01}, {a10, a11}};
            #pragma unroll
            for (int rr = 0; rr < 2; rr++) {
                const int row = r0 + rbase + rr;
                float4 res = ((const float4*)node_h)[(size_t)row * HV4 + lane];
                float4 v;
                v.x = res.x + ull_lo(accs[rr][0]) + bias.x;
                v.y = res.y + ull_hi(accs[rr][0]) + bias.y;
                v.z = res.z + ull_lo(accs[rr][1]) + bias.z;
                v.w = res.w + ull_hi(accs[rr][1]) + bias.w;
                float s    = v.x + v.y + v.z + v.w;
                float ssum = v.x * v.x + v.y * v.y + v.z * v.z + v.w * v.w;
                #pragma unroll
                for (int off = 16; off; off >>= 1) {
                    s    += __shfl_xor_sync(0xffffffffu, s, off);
                    ssum += __shfl_xor_sync(0xffffffffu, ssum, off);
                }
                const float mean = s * (1.f / 128.f);
                const float var  = ssum * (1.f / 128.f) - mean * mean;
                const float rstd = rsqrtf(var + 1e-6f);
                float4 o;
                o.x = fmaxf((v.x - mean) * rstd * sc.x + bi.x, 0.f);
                o.y = fmaxf((v.y - mean) * rstd * sc.y + bi.y, 0.f);
                o.z = fmaxf((v.z - mean) * rstd * sc.z + bi.z, 0.f);
                o.w = fmaxf((v.w - mean) * rstd * sc.w + bi.w, 0.f);
                ((float4*)out)[(size_t)row * HV4 + lane] = o;
                if (!LAST) {
                    float s1 = o.x * wsA.x + o.y * wsA.y + o.z * wsA.z + o.w * wsA.w;
                    float s2 = o.x * wdA.x + o.y * wdA.y + o.z * wdA.z + o.w * wdA.w;
                    #pragma unroll
                    for (int off = 16; off; off >>= 1) {
                        s1 += __shfl_xor_sync(0xffffffffu, s1, off);
                        s2 += __shfl_xor_sync(0xffffffffu, s2, off);
                    }
                    if (lane == 0) sdot2[row] = make_float2(s1, s2);
                }
            }
        }
    }
}

extern "C" void kernel_launch(void* const* d_in, const int* in_sizes, int n_in,
                              void* d_out, int out_size)
{
    const float* node_features = (const float*)d_in[0];
    const float* edge_features = (const float*)d_in[1];
    const int*   edge_indices  = (const int*)d_in[2];
    const float* W_node   = (const float*)d_in[3];
    const float* b_node   = (const float*)d_in[4];
    const float* W_edge   = (const float*)d_in[5];
    const float* b_edge   = (const float*)d_in[6];
    const float* W_gnn    = (const float*)d_in[7];
    const float* b_gnn    = (const float*)d_in[8];
    const float* W_top    = (const float*)d_in[9];
    const float* b_top    = (const float*)d_in[10];
    const float* ln_scale = (const float*)d_in[11];
    const float* ln_bias  = (const float*)d_in[12];

    float *node_h, *agg, *agg_base, *escratch, *edot, *wcombo;
    cudaGetSymbolAddress((void**)&node_h,   g_node_h);
    cudaGetSymbolAddress((void**)&agg,      g_agg);
    cudaGetSymbolAddress((void**)&agg_base, g_agg_base);
    cudaGetSymbolAddress((void**)&escratch, g_escratch);
    cudaGetSymbolAddress((void**)&edot,     g_edot);
    cudaGetSymbolAddress((void**)&wcombo,   g_wcombo);
    float* eaggF   = escratch;             // [NN, 64] (precompute phase)
    float* deg     = escratch + NN * 64;   // [NN]
    float2* sdot2  = (float2*)escratch;    // [NN] (layer phase; reuses eaggF region)

    float* out_node = (float*)d_out;                       // [NN, H]
    float* out_ew   = (float*)d_out + (size_t)NN * H;      // [NE]

    const int* srcp = edge_indices;
    const int* dstp = edge_indices + NE;

    const int smem_e128 = (128 * H + 32 * 128) * 4;        // 80 KB
    const int smem_e64  = (64 * H + 32 * 64) * 4;          // 40 KB
    const int smem_gnn  = 256 * H * 4 + 32 * 256 * 8;      // 128 + 64 = 192 KB
    cudaFuncSetAttribute((const void*)embed_kernel<128, false, true>,
                         cudaFuncAttributeMaxDynamicSharedMemorySize, smem_e128);
    cudaFuncSetAttribute((const void*)embed_kernel<64, true, false>,
                         cudaFuncAttributeMaxDynamicSharedMemorySize, smem_e64);
    cudaFuncSetAttribute((const void*)gnn_kernel<false>,
                         cudaFuncAttributeMaxDynamicSharedMemorySize, smem_gnn);
    cudaFuncSetAttribute((const void*)gnn_kernel<true>,
                         cudaFuncAttributeMaxDynamicSharedMemorySize, smem_gnn);

    // --- one-time precompute ---
    combo_kernel<<<1, 64>>>(W_edge, W_top, b_edge, b_top, wcombo);
    zero_kernel<<<(NN * 65 / 4 + 255) / 256, 256>>>((float4*)escratch, NN * 65 / 4);
    zero_kernel<<<NN * H / 4 / 256, 256>>>((float4*)agg, NN * H / 4);
    edge_pre_kernel<<<NE / 8, 256>>>(edge_features, dstp, wcombo, eaggF, deg, edot);
    embed_kernel<64, true, false><<<512, 256, smem_e64>>>(
        eaggF, W_edge, b_edge, deg, nullptr, agg_base, nullptr, NN);
    embed_kernel<128, false, true><<<512, 256, smem_e128>>>(
        node_features, W_node, b_node, nullptr, W_top, node_h, sdot2, NN);

    // --- layers ---
    for (int i = 0; i < 3; i++) {
        if (i == 2)
            edge_slim_kernel<true><<<NE / 8, 256>>>(node_h, srcp, dstp, sdot2, edot, agg, out_ew);
        else
            edge_slim_kernel<false><<<NE / 8, 256>>>(node_h, srcp, dstp, sdot2, edot, agg, out_ew);
        const float* Wl  = W_gnn + (size_t)i * 256 * H;
        const float* bl  = b_gnn + i * H;
        const float* lsl = ln_scale + i * H;
        const float* lbl = ln_bias + i * H;
        if (i == 2)
            gnn_kernel<true><<<148, 512, smem_gnn>>>(node_h, agg, agg_base, Wl, bl, lsl, lbl,
                                                     W_top, out_node, sdot2, NN);
        else
            gnn_kernel<false><<<148, 512, smem_gnn>>>(node_h, agg, agg_base, Wl, bl, lsl, lbl,
                                                      W_top, node_h, sdot2, NN);
    }
}

// round 9
// speedup vs baseline: 1.2469x; 1.2469x over previous
#include <cuda_runtime.h>
#include <cuda_bf16.h>
#include <cstdint>

#define NN 50000
#define NE 200000
#define H  128
#define HV4 32   // H/4

// Scratch (device globals: allocation-free per harness rules)
__device__ float g_node_h[NN * H];        // 25.6 MB
__device__ float g_agg[NN * H];           // 25.6 MB  per-layer atomic accumulator
__device__ float g_agg_base[NN * H];      // 25.6 MB  Σ edge_h per dst (factorized)
__device__ float g_escratch[NN * 65];     // precompute: eaggF [NN,64] + deg [NN]; layers: sdot2 [NN]
__device__ float g_edot[NE];              // folded edge-constant gate logit
__device__ float g_wcombo[65];            // W_edge @ w_top_e (64) + folded bias

__device__ __forceinline__ void fma4(float4& acc, const float4& wv, float s) {
    acc.x += wv.x * s;
    acc.y += wv.y * s;
    acc.z += wv.z * s;
    acc.w += wv.w * s;
}
__device__ __forceinline__ void red_v4(float* p, float a, float b, float c, float d) {
    asm volatile("red.global.add.v4.f32 [%0], {%1,%2,%3,%4};"
                 :: "l"(p), "f"(a), "f"(b), "f"(c), "f"(d) : "memory");
}
__device__ __forceinline__ void red_v2(float* p, float a, float b) {
    asm volatile("red.global.add.v2.f32 [%0], {%1,%2};"
                 :: "l"(p), "f"(a), "f"(b) : "memory");
}
// pack two floats into bf16x2 (lo -> low 16 bits)
__device__ __forceinline__ uint32_t bf16pack(float a, float b) {
    uint32_t r;
    asm("{.reg .b16 x, y; cvt.rn.bf16.f32 x, %1; cvt.rn.bf16.f32 y, %2; mov.b32 %0, {x, y};}"
        : "=r"(r) : "f"(a), "f"(b));
    return r;
}
__device__ __forceinline__ void mma16816(float* c,
                                         uint32_t a0, uint32_t a1, uint32_t a2, uint32_t a3,
                                         uint32_t b0, uint32_t b1) {
    asm("mma.sync.aligned.m16n8k16.row.col.f32.bf16.bf16.f32 "
        "{%0,%1,%2,%3}, {%4,%5,%6,%7}, {%8,%9}, {%0,%1,%2,%3};"
        : "+f"(c[0]), "+f"(c[1]), "+f"(c[2]), "+f"(c[3])
        : "r"(a0), "r"(a1), "r"(a2), "r"(a3), "r"(b0), "r"(b1));
}

__global__ void zero_kernel(float4* __restrict__ p, int n4) {
    int i = blockIdx.x * blockDim.x + threadIdx.x;
    if (i < n4) p[i] = make_float4(0.f, 0.f, 0.f, 0.f);
}

// ---------------------------------------------------------------------------
__global__ void combo_kernel(const float* __restrict__ W_edge,
                             const float* __restrict__ W_top,
                             const float* __restrict__ b_edge,
                             const float* __restrict__ b_top,
                             float* __restrict__ wcombo)
{
    const int k = threadIdx.x;   // 64 threads
    float s = 0.f;
    for (int h = 0; h < H; h++) s += W_edge[k * H + h] * W_top[2 * H + h];
    wcombo[k] = s;
    if (k == 0) {
        float b = b_top[0];
        for (int h = 0; h < H; h++) b += b_edge[h] * W_top[2 * H + h];
        wcombo[64] = b;
    }
}

// ---------------------------------------------------------------------------
__global__ void edge_pre_kernel(const float* __restrict__ ef,
                                const int* __restrict__ dst,
                                const float* __restrict__ wcombo,
                                float* __restrict__ eaggF,
                                float* __restrict__ deg,
                                float* __restrict__ edot)
{
    __shared__ float wsh[65];
    const int tid  = threadIdx.x;
    const int lane = tid & 31;
    const int wid  = tid >> 5;
    if (tid < 65) wsh[tid] = wcombo[tid];
    __syncthreads();

    const int e = blockIdx.x * 8 + wid;
    const int d = dst[e];
    float2 v = ((const float2*)ef)[(size_t)e * 32 + lane];
    float p = v.x * wsh[lane * 2] + v.y * wsh[lane * 2 + 1];
    #pragma unroll
    for (int off = 16; off; off >>= 1)
        p += __shfl_xor_sync(0xffffffffu, p, off);
    if (lane == 0) {
        edot[e] = p + wsh[64];
        atomicAdd(deg + d, 1.f);
    }
    red_v2(eaggF + (size_t)d * 64 + lane * 2, v.x, v.y);
}

// ---------------------------------------------------------------------------
// Embed GEMM (R3-proven): out[rows,H] = X[rows,K] @ W[K,H] + scale*b
// ---------------------------------------------------------------------------
template<int K, bool DEGBIAS, bool SDOT>
__global__ void embed_kernel(const float* __restrict__ X,
                             const float* __restrict__ W,
                             const float* __restrict__ b,
                             const float* __restrict__ deg,
                             const float* __restrict__ W_top,
                             float* __restrict__ out,
                             float2* __restrict__ sdot2, int rows)
{
    extern __shared__ float sm[];
    float* Wsh  = sm;            // K*H floats
    float* xbuf = sm + K * H;    // 32*K floats

    const int tid  = threadIdx.x;
    const int lane = tid & 31;
    const int wid  = tid >> 5;

    for (int i = tid; i < K * H / 4; i += 256)
        ((float4*)Wsh)[i] = ((const float4*)W)[i];
    const float4 bias = ((const float4*)b)[lane];
    float4 wsA, wdA;
    if (SDOT) {
        wsA = ((const float4*)W_top)[lane];
        wdA = ((const float4*)W_top)[32 + lane];
    }

    for (int r0 = blockIdx.x * 32; r0 < rows; r0 += gridDim.x * 32) {
        __syncthreads();
        const int nrows = min(32, rows - r0);
        for (int i = tid; i < nrows * (K / 4); i += 256)
            ((float4*)xbuf)[i] = ((const float4*)(X + (size_t)r0 * K))[i];
        __syncthreads();

        const int rbase = wid * 4;
        if (rbase < nrows) {
            float4 acc0 = make_float4(0.f, 0.f, 0.f, 0.f);
            float4 acc1 = acc0, acc2 = acc0, acc3 = acc0;
            const float* xr0 = xbuf + (rbase + 0) * K;
            const float* xr1 = xbuf + (rbase + 1) * K;
            const float* xr2 = xbuf + (rbase + 2) * K;
            const float* xr3 = xbuf + (rbase + 3) * K;
            #pragma unroll 4
            for (int k = 0; k < K; k++) {
                float4 wv = ((float4*)Wsh)[k * HV4 + lane];
                fma4(acc0, wv, xr0[k]);
                fma4(acc1, wv, xr1[k]);
                fma4(acc2, wv, xr2[k]);
                fma4(acc3, wv, xr3[k]);
            }
            float4 accs[4] = {acc0, acc1, acc2, acc3};
            #pragma unroll
            for (int rr = 0; rr < 4; rr++) {
                const float scb = DEGBIAS ? deg[r0 + rbase + rr] : 1.f;
                float4 o;
                o.x = accs[rr].x + scb * bias.x;
                o.y = accs[rr].y + scb * bias.y;
                o.z = accs[rr].z + scb * bias.z;
                o.w = accs[rr].w + scb * bias.w;
                ((float4*)out)[(size_t)(r0 + rbase + rr) * HV4 + lane] = o;
                if (SDOT) {
                    float s1 = o.x * wsA.x + o.y * wsA.y + o.z * wsA.z + o.w * wsA.w;
                    float s2 = o.x * wdA.x + o.y * wdA.y + o.z * wdA.z + o.w * wdA.w;
                    #pragma unroll
                    for (int off = 16; off; off >>= 1) {
                        s1 += __shfl_xor_sync(0xffffffffu, s1, off);
                        s2 += __shfl_xor_sync(0xffffffffu, s2, off);
                    }
                    if (lane == 0) sdot2[r0 + rbase + rr] = make_float2(s1, s2);
                }
            }
        }
    }
}

// ---------------------------------------------------------------------------
// Slim per-layer edge kernel (unchanged, measured-good).
// ---------------------------------------------------------------------------
template<bool WRITE_EW>
__global__ void edge_slim_kernel(const float* __restrict__ node_h,
                                 const int* __restrict__ src,
                                 const int* __restrict__ dst,
                                 const float2* __restrict__ sdot2,
                                 const float* __restrict__ edot,
                                 float* __restrict__ agg,
                                 float* __restrict__ ew)
{
    const int tid  = threadIdx.x;
    const int lane = tid & 31;
    const int wid  = tid >> 5;
    const int e = blockIdx.x * 8 + wid;

    const int s = src[e];
    const int d = dst[e];
    const float2 ss = sdot2[s];
    const float2 dd = sdot2[d];
    const float p = ss.x + dd.y + edot[e];
    const float w = 1.f / (1.f + __expf(-p));

    float4 sf = ((const float4*)node_h)[(size_t)s * HV4 + lane];
    red_v4(agg + (size_t)d * H + lane * 4, sf.x * w, sf.y * w, sf.z * w, sf.w * w);

    if (WRITE_EW && lane == 0) ew[e] = w;
}

// ---------------------------------------------------------------------------
// GNN via bf16-split tensor-core MMA.
// updated = [node_h | agg+agg_base] @ W[256,128] + b;
// out = relu(LN(node_h + updated)); sdot2 epilogue; clears agg.
// Split: x = hi + lo (bf16 each), W likewise. D = xh*Wh + xh*Wl + xl*Wh.
// Persistent: 148 blocks x 256 thr. Warp tile: 16 rows x 64 cols.
// All global reads row-clamped to nrows-1 in the tail chunk.
// ---------------------------------------------------------------------------
#define A_STR 73     // uint32 stride per k-pair row (64 rows + pad)
#define B_STR 136    // uint32 stride per k-pair row (128 cols + pad)
#define A_PLANE (128 * A_STR)
#define B_PLANE (128 * B_STR)
#define SMEM_TC ((2 * A_PLANE + 2 * B_PLANE + 640 + 512 + 512) * 4)

template<bool LAST>
__global__ void __launch_bounds__(256, 1)
gnn_tc_kernel(const float* __restrict__ node_h,
              float* __restrict__ agg,
              const float* __restrict__ agg_base,
              const float* __restrict__ W,      // [256,128]
              const float* __restrict__ b,
              const float* __restrict__ lns,
              const float* __restrict__ lnb,
              const float* __restrict__ W_top,
              float* __restrict__ out,
              float2* __restrict__ sdot2, int rows)
{
    extern __shared__ uint32_t smu[];
    uint32_t* Ahi = smu;
    uint32_t* Alo = Ahi + A_PLANE;
    uint32_t* Bhi = Alo + A_PLANE;
    uint32_t* Blo = Bhi + B_PLANE;
    float*    prm = (float*)(Blo + B_PLANE);        // 640 floats: b|lns|lnb|ws|wd
    float2*   red = (float2*)(prm + 640);           // [64 rows][2 halves] (s,ssum)
    float2*   sdp = red + 128;                      // [64 rows][2 halves] (s1,s2)

    const int tid  = threadIdx.x;
    const int lane = tid & 31;
    const int w    = tid >> 5;
    const int t4   = lane & 3;
    const int g    = lane >> 2;

    const float2* nh2  = (const float2*)node_h;
    float2*       ag2  = (float2*)agg;
    const float2* agb2 = (const float2*)agg_base;
    float2*       outp2 = (float2*)out;
    const float2* prm2 = (const float2*)prm;

    // ---- stage W (once): packed bf16x2 hi/lo planes ----
    for (int i = tid; i < 128 * 128; i += 256) {
        const int kp = i >> 7, n = i & 127;
        const float w0 = W[(size_t)(2 * kp) * 128 + n];
        const float w1 = W[(size_t)(2 * kp + 1) * 128 + n];
        const float h0 = __bfloat162float(__float2bfloat16_rn(w0));
        const float h1 = __bfloat162float(__float2bfloat16_rn(w1));
        Bhi[kp * B_STR + n] = bf16pack(h0, h1);
        Blo[kp * B_STR + n] = bf16pack(w0 - h0, w1 - h1);
    }
    for (int i = tid; i < 128; i += 256) {
        prm[i]       = b[i];
        prm[128 + i] = lns[i];
        prm[256 + i] = lnb[i];
        prm[384 + i] = W_top[i];
        prm[512 + i] = W_top[128 + i];
    }

    const int roffL = (w >> 1) * 16;
    const int noff  = (w & 1) * 64;

    for (int r0 = blockIdx.x * 64; r0 < rows; r0 += gridDim.x * 64) {
        __syncthreads();   // protect prior chunk's smem reads + first-iter W staging
        const int nrows = min(64, rows - r0);

        // ---- stage x = [node_h | agg+agg_base] as bf16x2 hi/lo; clear agg ----
        for (int i = tid; i < nrows * 128; i += 256) {
            const int r = i >> 7, kp = i & 127;
            float2 v;
            if (kp < 64) {
                v = nh2[(size_t)(r0 + r) * 64 + kp];
            } else {
                const int c = kp - 64;
                float2 a  = ag2[(size_t)(r0 + r) * 64 + c];
                float2 ab = agb2[(size_t)(r0 + r) * 64 + c];
                v.x = a.x + ab.x;
                v.y = a.y + ab.y;
                if (!LAST) ag2[(size_t)(r0 + r) * 64 + c] = make_float2(0.f, 0.f);
            }
            const float h0 = __bfloat162float(__float2bfloat16_rn(v.x));
            const float h1 = __bfloat162float(__float2bfloat16_rn(v.y));
            Ahi[kp * A_STR + r] = bf16pack(h0, h1);
            Alo[kp * A_STR + r] = bf16pack(v.x - h0, v.y - h1);
        }
        // zero-fill stale tail rows so MMA accumulators stay finite
        if (nrows < 64) {
            for (int i = tid; i < (64 - nrows) * 128; i += 256) {
                const int r = nrows + (i >> 7), kp = i & 127;
                Ahi[kp * A_STR + r] = 0u;
                Alo[kp * A_STR + r] = 0u;
            }
        }
        __syncthreads();

        // ---- MMA mainloop: C[8 n-tiles][4] ----
        float c[8][4];
        #pragma unroll
        for (int nt = 0; nt < 8; nt++)
            c[nt][0] = c[nt][1] = c[nt][2] = c[nt][3] = 0.f;

        #pragma unroll 2
        for (int k = 0; k < 16; k++) {
            const int kp0 = 8 * k + t4;
            const uint32_t ah0 = Ahi[kp0 * A_STR + roffL + g];
            const uint32_t ah1 = Ahi[kp0 * A_STR + roffL + g + 8];
            const uint32_t ah2 = Ahi[(kp0 + 4) * A_STR + roffL + g];
            const uint32_t ah3 = Ahi[(kp0 + 4) * A_STR + roffL + g + 8];
            const uint32_t al0 = Alo[kp0 * A_STR + roffL + g];
            const uint32_t al1 = Alo[kp0 * A_STR + roffL + g + 8];
            const uint32_t al2 = Alo[(kp0 + 4) * A_STR + roffL + g];
            const uint32_t al3 = Alo[(kp0 + 4) * A_STR + roffL + g + 8];
            const uint32_t* B0h = Bhi + kp0 * B_STR + noff + g;
            const uint32_t* B1h = Bhi + (kp0 + 4) * B_STR + noff + g;
            const uint32_t* B0l = Blo + kp0 * B_STR + noff + g;
            const uint32_t* B1l = Blo + (kp0 + 4) * B_STR + noff + g;
            #pragma unroll
            for (int nt = 0; nt < 8; nt++) {
                const uint32_t bh0 = B0h[nt * 8];
                const uint32_t bh1 = B1h[nt * 8];
                const uint32_t bl0 = B0l[nt * 8];
                const uint32_t bl1 = B1l[nt * 8];
                mma16816(c[nt], ah0, ah1, ah2, ah3, bh0, bh1);
                mma16816(c[nt], ah0, ah1, ah2, ah3, bl0, bl1);
                mma16816(c[nt], al0, al1, al2, al3, bh0, bh1);
            }
        }

        // ---- epilogue: residual + bias, LN partials (reads row-clamped) ----
        const int lr0 = roffL + g;
        const int lr1 = roffL + g + 8;
        const size_t gr0 = (size_t)r0 + min(lr0, nrows - 1);
        const size_t gr1 = (size_t)r0 + min(lr1, nrows - 1);
        const int colh0 = (w & 1) * 32 + t4;

        float2 v0[8], v1[8];
        float s0 = 0.f, ss0 = 0.f, s1r = 0.f, ss1r = 0.f;
        #pragma unroll
        for (int nt = 0; nt < 8; nt++) {
            const int ch = colh0 + nt * 4;
            const float2 res0 = nh2[gr0 * 64 + ch];
            const float2 res1 = nh2[gr1 * 64 + ch];
            const float2 bia  = prm2[ch];
            float2 a0v, a1v;
            a0v.x = c[nt][0] + res0.x + bia.x;
            a0v.y = c[nt][1] + res0.y + bia.y;
            a1v.x = c[nt][2] + res1.x + bia.x;
            a1v.y = c[nt][3] + res1.y + bia.y;
            v0[nt] = a0v;
            v1[nt] = a1v;
            s0  += a0v.x + a0v.y;  ss0  += a0v.x * a0v.x + a0v.y * a0v.y;
            s1r += a1v.x + a1v.y;  ss1r += a1v.x * a1v.x + a1v.y * a1v.y;
        }
        #pragma unroll
        for (int off = 1; off <= 2; off <<= 1) {
            s0   += __shfl_xor_sync(0xffffffffu, s0, off);
            ss0  += __shfl_xor_sync(0xffffffffu, ss0, off);
            s1r  += __shfl_xor_sync(0xffffffffu, s1r, off);
            ss1r += __shfl_xor_sync(0xffffffffu, ss1r, off);
        }
        if (t4 == 0) {
            red[lr0 * 2 + (w & 1)] = make_float2(s0, ss0);
            red[lr1 * 2 + (w & 1)] = make_float2(s1r, ss1r);
        }
        __syncthreads();

        const float2 pa = red[lr0 * 2 + 0], pb = red[lr0 * 2 + 1];
        const float2 qa = red[lr1 * 2 + 0], qb = red[lr1 * 2 + 1];
        const float mean0 = (pa.x + pb.x) * (1.f / 128.f);
        const float var0  = (pa.y + pb.y) * (1.f / 128.f) - mean0 * mean0;
        const float rstd0 = rsqrtf(var0 + 1e-6f);
        const float mean1 = (qa.x + qb.x) * (1.f / 128.f);
        const float var1  = (qa.y + qb.y) * (1.f / 128.f) - mean1 * mean1;
        const float rstd1 = rsqrtf(var1 + 1e-6f);

        float d0s = 0.f, d0d = 0.f, d1s = 0.f, d1d = 0.f;
        #pragma unroll
        for (int nt = 0; nt < 8; nt++) {
            const int ch = colh0 + nt * 4;
            const float2 sc2 = prm2[64 + ch];
            const float2 bi2 = prm2[128 + ch];
            float2 o0, o1;
            o0.x = fmaxf((v0[nt].x - mean0) * rstd0 * sc2.x + bi2.x, 0.f);
            o0.y = fmaxf((v0[nt].y - mean0) * rstd0 * sc2.y + bi2.y, 0.f);
            o1.x = fmaxf((v1[nt].x - mean1) * rstd1 * sc2.x + bi2.x, 0.f);
            o1.y = fmaxf((v1[nt].y - mean1) * rstd1 * sc2.y + bi2.y, 0.f);
            if (lr0 < nrows) outp2[((size_t)r0 + lr0) * 64 + ch] = o0;
            if (lr1 < nrows) outp2[((size_t)r0 + lr1) * 64 + ch] = o1;
            if (!LAST) {
                const float2 ws2 = prm2[192 + ch];
                const float2 wd2 = prm2[256 + ch];
                d0s += o0.x * ws2.x + o0.y * ws2.y;
                d0d += o0.x * wd2.x + o0.y * wd2.y;
                d1s += o1.x * ws2.x + o1.y * ws2.y;
                d1d += o1.x * wd2.x + o1.y * wd2.y;
            }
        }
        if (!LAST) {
            #pragma unroll
            for (int off = 1; off <= 2; off <<= 1) {
                d0s += __shfl_xor_sync(0xffffffffu, d0s, off);
                d0d += __shfl_xor_sync(0xffffffffu, d0d, off);
                d1s += __shfl_xor_sync(0xffffffffu, d1s, off);
                d1d += __shfl_xor_sync(0xffffffffu, d1d, off);
            }
            if (t4 == 0) {
                sdp[lr0 * 2 + (w & 1)] = make_float2(d0s, d0d);
                sdp[lr1 * 2 + (w & 1)] = make_float2(d1s, d1d);
            }
            __syncthreads();
            if (tid < 64 && tid < nrows) {
                const float2 a = sdp[tid * 2 + 0];
                const float2 bb = sdp[tid * 2 + 1];
                sdot2[r0 + tid] = make_float2(a.x + bb.x, a.y + bb.y);
            }
        }
    }
}

extern "C" void kernel_launch(void* const* d_in, const int* in_sizes, int n_in,
                              void* d_out, int out_size)
{
    const float* node_features = (const float*)d_in[0];
    const float* edge_features = (const float*)d_in[1];
    const int*   edge_indices  = (const int*)d_in[2];
    const float* W_node   = (const float*)d_in[3];
    const float* b_node   = (const float*)d_in[4];
    const float* W_edge   = (const float*)d_in[5];
    const float* b_edge   = (const float*)d_in[6];
    const float* W_gnn    = (const float*)d_in[7];
    const float* b_gnn    = (const float*)d_in[8];
    const float* W_top    = (const float*)d_in[9];
    const float* b_top    = (const float*)d_in[10];
    const float* ln_scale = (const float*)d_in[11];
    const float* ln_bias  = (const float*)d_in[12];

    float *node_h, *agg, *agg_base, *escratch, *edot, *wcombo;
    cudaGetSymbolAddress((void**)&node_h,   g_node_h);
    cudaGetSymbolAddress((void**)&agg,      g_agg);
    cudaGetSymbolAddress((void**)&agg_base, g_agg_base);
    cudaGetSymbolAddress((void**)&escratch, g_escratch);
    cudaGetSymbolAddress((void**)&edot,     g_edot);
    cudaGetSymbolAddress((void**)&wcombo,   g_wcombo);
    float* eaggF   = escratch;             // [NN, 64] (precompute phase)
    float* deg     = escratch + NN * 64;   // [NN]
    float2* sdot2  = (float2*)escratch;    // [NN] (layer phase; reuses eaggF region)

    float* out_node = (float*)d_out;                       // [NN, H]
    float* out_ew   = (float*)d_out + (size_t)NN * H;      // [NE]

    const int* srcp = edge_indices;
    const int* dstp = edge_indices + NE;

    const int smem_e128 = (128 * H + 32 * 128) * 4;        // 80 KB
    const int smem_e64  = (64 * H + 32 * 64) * 4;          // 40 KB
    cudaFuncSetAttribute((const void*)embed_kernel<128, false, true>,
                         cudaFuncAttributeMaxDynamicSharedMemorySize, smem_e128);
    cudaFuncSetAttribute((const void*)embed_kernel<64, true, false>,
                         cudaFuncAttributeMaxDynamicSharedMemorySize, smem_e64);
    cudaFuncSetAttribute((const void*)gnn_tc_kernel<false>,
                         cudaFuncAttributeMaxDynamicSharedMemorySize, SMEM_TC);
    cudaFuncSetAttribute((const void*)gnn_tc_kernel<true>,
                         cudaFuncAttributeMaxDynamicSharedMemorySize, SMEM_TC);

    // --- one-time precompute ---
    combo_kernel<<<1, 64>>>(W_edge, W_top, b_edge, b_top, wcombo);
    zero_kernel<<<(NN * 65 / 4 + 255) / 256, 256>>>((float4*)escratch, NN * 65 / 4);
    zero_kernel<<<NN * H / 4 / 256, 256>>>((float4*)agg, NN * H / 4);
    edge_pre_kernel<<<NE / 8, 256>>>(edge_features, dstp, wcombo, eaggF, deg, edot);
    embed_kernel<64, true, false><<<512, 256, smem_e64>>>(
        eaggF, W_edge, b_edge, deg, nullptr, agg_base, nullptr, NN);
    embed_kernel<128, false, true><<<512, 256, smem_e128>>>(
        node_features, W_node, b_node, nullptr, W_top, node_h, sdot2, NN);

    // --- layers ---
    for (int i = 0; i < 3; i++) {
        if (i == 2)
            edge_slim_kernel<true><<<NE / 8, 256>>>(node_h, srcp, dstp, sdot2, edot, agg, out_ew);
        else
            edge_slim_kernel<false><<<NE / 8, 256>>>(node_h, srcp, dstp, sdot2, edot, agg, out_ew);
        const float* Wl  = W_gnn + (size_t)i * 256 * H;
        const float* bl  = b_gnn + i * H;
        const float* lsl = ln_scale + i * H;
        const float* lbl = ln_bias + i * H;
        if (i == 2)
            gnn_tc_kernel<true><<<148, 256, SMEM_TC>>>(node_h, agg, agg_base, Wl, bl, lsl, lbl,
                                                       W_top, out_node, sdot2, NN);
        else
            gnn_tc_kernel<false><<<148, 256, SMEM_TC>>>(node_h, agg, agg_base, Wl, bl, lsl, lbl,
                                                        W_top, node_h, sdot2, NN);
    }
}

// round 10
// speedup vs baseline: 1.2556x; 1.0070x over previous
#include <cuda_runtime.h>
#include <cuda_bf16.h>
#include <cstdint>

#define NN 50000
#define NE 200000
#define H  128
#define HV4 32   // H/4

// Scratch (device globals: allocation-free per harness rules)
__device__ float g_node_h[NN * H];        // 25.6 MB  node_h buffer A
__device__ float g_node_h2[NN * H];       // 25.6 MB  node_h buffer B (ping-pong)
__device__ float g_agg_base[NN * H];      // 25.6 MB  Σ edge_h per dst (factorized)
__device__ float g_escratch[NN * 65];     // precompute: eaggF [NN,64] + deg [NN]; layers: sdot_a|sdot_b
__device__ float g_edot[NE];              // folded edge-constant gate logit
__device__ float g_wcombo[65];            // W_edge @ w_top_e (64) + folded bias
// CSR (dst-sorted edge list), built once per call
__device__ int   g_cnt[NN];
__device__ int   g_off[NN + 1];
__device__ int   g_cur[NN];
__device__ int   g_src_csr[NE];
__device__ int   g_eid_csr[NE];
__device__ float g_edot_csr[NE];

__device__ __forceinline__ void fma4(float4& acc, const float4& wv, float s) {
    acc.x += wv.x * s;
    acc.y += wv.y * s;
    acc.z += wv.z * s;
    acc.w += wv.w * s;
}
__device__ __forceinline__ void red_v2(float* p, float a, float b) {
    asm volatile("red.global.add.v2.f32 [%0], {%1,%2};"
                 :: "l"(p), "f"(a), "f"(b) : "memory");
}
__device__ __forceinline__ uint32_t bf16pack(float a, float b) {
    uint32_t r;
    asm("{.reg .b16 x, y; cvt.rn.bf16.f32 x, %1; cvt.rn.bf16.f32 y, %2; mov.b32 %0, {x, y};}"
        : "=r"(r) : "f"(a), "f"(b));
    return r;
}
__device__ __forceinline__ float bf16rn(float x) {
    return __bfloat162float(__float2bfloat16_rn(x));
}
__device__ __forceinline__ void mma16816(float* c,
                                         uint32_t a0, uint32_t a1, uint32_t a2, uint32_t a3,
                                         uint32_t b0, uint32_t b1) {
    asm("mma.sync.aligned.m16n8k16.row.col.f32.bf16.bf16.f32 "
        "{%0,%1,%2,%3}, {%4,%5,%6,%7}, {%8,%9}, {%0,%1,%2,%3};"
        : "+f"(c[0]), "+f"(c[1]), "+f"(c[2]), "+f"(c[3])
        : "r"(a0), "r"(a1), "r"(a2), "r"(a3), "r"(b0), "r"(b1));
}

__global__ void zero_kernel(float4* __restrict__ p, int n4) {
    int i = blockIdx.x * blockDim.x + threadIdx.x;
    if (i < n4) p[i] = make_float4(0.f, 0.f, 0.f, 0.f);
}

// ---------------------------------------------------------------------------
__global__ void combo_kernel(const float* __restrict__ W_edge,
                             const float* __restrict__ W_top,
                             const float* __restrict__ b_edge,
                             const float* __restrict__ b_top,
                             float* __restrict__ wcombo)
{
    const int k = threadIdx.x;   // 64 threads
    float s = 0.f;
    for (int h = 0; h < H; h++) s += W_edge[k * H + h] * W_top[2 * H + h];
    wcombo[k] = s;
    if (k == 0) {
        float b = b_top[0];
        for (int h = 0; h < H; h++) b += b_edge[h] * W_top[2 * H + h];
        wcombo[64] = b;
    }
}

// ---------------------------------------------------------------------------
// Per-edge precompute (once): edot, eaggF scatter, deg (float), cnt (int).
// ---------------------------------------------------------------------------
__global__ void edge_pre_kernel(const float* __restrict__ ef,
                                const int* __restrict__ dst,
                                const float* __restrict__ wcombo,
                                float* __restrict__ eaggF,
                                float* __restrict__ deg,
                                int* __restrict__ cnt,
                                float* __restrict__ edot)
{
    __shared__ float wsh[65];
    const int tid  = threadIdx.x;
    const int lane = tid & 31;
    const int wid  = tid >> 5;
    if (tid < 65) wsh[tid] = wcombo[tid];
    __syncthreads();

    const int e = blockIdx.x * 8 + wid;
    const int d = dst[e];
    float2 v = ((const float2*)ef)[(size_t)e * 32 + lane];
    float p = v.x * wsh[lane * 2] + v.y * wsh[lane * 2 + 1];
    #pragma unroll
    for (int off = 16; off; off >>= 1)
        p += __shfl_xor_sync(0xffffffffu, p, off);
    if (lane == 0) {
        edot[e] = p + wsh[64];
        atomicAdd(deg + d, 1.f);
        atomicAdd(cnt + d, 1);
    }
    red_v2(eaggF + (size_t)d * 64 + lane * 2, v.x, v.y);
}

// ---------------------------------------------------------------------------
// CSR build: exclusive scan of cnt -> off, cur. Single block, 1024 threads.
// ---------------------------------------------------------------------------
__global__ void scan_kernel(const int* __restrict__ cnt,
                            int* __restrict__ off,
                            int* __restrict__ cur)
{
    __shared__ int sums[1024];
    const int t = threadIdx.x;
    const int CH = (NN + 1023) / 1024;   // 49
    const int base = t * CH;
    int s = 0;
    for (int i = 0; i < CH; i++) {
        const int idx = base + i;
        if (idx < NN) s += cnt[idx];
    }
    sums[t] = s;
    __syncthreads();
    int x = s;
    for (int d = 1; d < 1024; d <<= 1) {
        const int y = (t >= d) ? sums[t - d] : 0;
        __syncthreads();
        x += y;
        sums[t] = x;
        __syncthreads();
    }
    int run = x - s;   // exclusive prefix
    for (int i = 0; i < CH; i++) {
        const int idx = base + i;
        if (idx < NN) {
            off[idx] = run;
            cur[idx] = run;
            run += cnt[idx];
        }
    }
    if (t == 1023) off[NN] = NE;
}

__global__ void scatter_kernel(const int* __restrict__ src,
                               const int* __restrict__ dst,
                               const float* __restrict__ edot,
                               int* __restrict__ cur,
                               int* __restrict__ src_csr,
                               int* __restrict__ eid_csr,
                               float* __restrict__ edot_csr)
{
    const int e = blockIdx.x * 256 + threadIdx.x;
    if (e >= NE) return;
    const int d = dst[e];
    const int pos = atomicAdd(cur + d, 1);
    src_csr[pos]  = src[e];
    eid_csr[pos]  = e;
    edot_csr[pos] = edot[e];
}

// ---------------------------------------------------------------------------
// Embed GEMM (R3-proven): out[rows,H] = X[rows,K] @ W[K,H] + scale*b
// ---------------------------------------------------------------------------
template<int K, bool DEGBIAS, bool SDOT>
__global__ void embed_kernel(const float* __restrict__ X,
                             const float* __restrict__ W,
                             const float* __restrict__ b,
                             const float* __restrict__ deg,
                             const float* __restrict__ W_top,
                             float* __restrict__ out,
                             float2* __restrict__ sdot2, int rows)
{
    extern __shared__ float sm[];
    float* Wsh  = sm;            // K*H floats
    float* xbuf = sm + K * H;    // 32*K floats

    const int tid  = threadIdx.x;
    const int lane = tid & 31;
    const int wid  = tid >> 5;

    for (int i = tid; i < K * H / 4; i += 256)
        ((float4*)Wsh)[i] = ((const float4*)W)[i];
    const float4 bias = ((const float4*)b)[lane];
    float4 wsA, wdA;
    if (SDOT) {
        wsA = ((const float4*)W_top)[lane];
        wdA = ((const float4*)W_top)[32 + lane];
    }

    for (int r0 = blockIdx.x * 32; r0 < rows; r0 += gridDim.x * 32) {
        __syncthreads();
        const int nrows = min(32, rows - r0);
        for (int i = tid; i < nrows * (K / 4); i += 256)
            ((float4*)xbuf)[i] = ((const float4*)(X + (size_t)r0 * K))[i];
        __syncthreads();

        const int rbase = wid * 4;
        if (rbase < nrows) {
            float4 acc0 = make_float4(0.f, 0.f, 0.f, 0.f);
            float4 acc1 = acc0, acc2 = acc0, acc3 = acc0;
            const float* xr0 = xbuf + (rbase + 0) * K;
            const float* xr1 = xbuf + (rbase + 1) * K;
            const float* xr2 = xbuf + (rbase + 2) * K;
            const float* xr3 = xbuf + (rbase + 3) * K;
            #pragma unroll 4
            for (int k = 0; k < K; k++) {
                float4 wv = ((float4*)Wsh)[k * HV4 + lane];
                fma4(acc0, wv, xr0[k]);
                fma4(acc1, wv, xr1[k]);
                fma4(acc2, wv, xr2[k]);
                fma4(acc3, wv, xr3[k]);
            }
            float4 accs[4] = {acc0, acc1, acc2, acc3};
            #pragma unroll
            for (int rr = 0; rr < 4; rr++) {
                const float scb = DEGBIAS ? deg[r0 + rbase + rr] : 1.f;
                float4 o;
                o.x = accs[rr].x + scb * bias.x;
                o.y = accs[rr].y + scb * bias.y;
                o.z = accs[rr].z + scb * bias.z;
                o.w = accs[rr].w + scb * bias.w;
                ((float4*)out)[(size_t)(r0 + rbase + rr) * HV4 + lane] = o;
                if (SDOT) {
                    float s1 = o.x * wsA.x + o.y * wsA.y + o.z * wsA.z + o.w * wsA.w;
                    float s2 = o.x * wdA.x + o.y * wdA.y + o.z * wdA.z + o.w * wdA.w;
                    #pragma unroll
                    for (int off = 16; off; off >>= 1) {
                        s1 += __shfl_xor_sync(0xffffffffu, s1, off);
                        s2 += __shfl_xor_sync(0xffffffffu, s2, off);
                    }
                    if (lane == 0) sdot2[r0 + rbase + rr] = make_float2(s1, s2);
                }
            }
        }
    }
}

// ---------------------------------------------------------------------------
// Fused GNN layer: CSR aggregation + bf16-split tensor-core GEMM + LN/ReLU.
// Reads nh_old / sdot_cur; writes nh_new / sdot_nxt (+ ew on last layer).
// Warp tile: 16 rows x 64 cols. Staging: warp owns 8 nodes; per node the
// warp seeds acc = agg_base[row] and accumulates w*nh_old[src] over the
// node's CSR edges (gates lane-parallel, gathers with 4-way ILP).
// ---------------------------------------------------------------------------
#define A_STR 73
#define B_STR 136
#define A_PLANE (128 * A_STR)
#define B_PLANE (128 * B_STR)
#define SMEM_TC ((2 * A_PLANE + 2 * B_PLANE + 640 + 512 + 512) * 4)

template<bool LAST>
__global__ void __launch_bounds__(256, 1)
gnn_fused_kernel(const float* __restrict__ nh_old,
                 float* __restrict__ nh_new,
                 const float* __restrict__ agg_base,
                 const int* __restrict__ off,
                 const int* __restrict__ src_csr,
                 const int* __restrict__ eid_csr,
                 const float* __restrict__ edot_csr,
                 const float2* __restrict__ sdot_cur,
                 float2* __restrict__ sdot_nxt,
                 const float* __restrict__ W,      // [256,128]
                 const float* __restrict__ b,
                 const float* __restrict__ lns,
                 const float* __restrict__ lnb,
                 const float* __restrict__ W_top,
                 float* __restrict__ ew, int rows)
{
    extern __shared__ uint32_t smu[];
    uint32_t* Ahi = smu;
    uint32_t* Alo = Ahi + A_PLANE;
    uint32_t* Bhi = Alo + A_PLANE;
    uint32_t* Blo = Bhi + B_PLANE;
    float*    prm = (float*)(Blo + B_PLANE);        // 640 floats: b|lns|lnb|ws|wd
    float2*   red = (float2*)(prm + 640);           // [64 rows][2 halves]
    float2*   sdp = red + 128;

    const int tid  = threadIdx.x;
    const int lane = tid & 31;
    const int w    = tid >> 5;
    const int t4   = lane & 3;
    const int g    = lane >> 2;

    const float2* nh2   = (const float2*)nh_old;
    float2*       outp2 = (float2*)nh_new;
    const float2* prm2  = (const float2*)prm;

    // ---- stage W (once): packed bf16x2 hi/lo planes ----
    for (int i = tid; i < 128 * 128; i += 256) {
        const int kp = i >> 7, n = i & 127;
        const float w0 = W[(size_t)(2 * kp) * 128 + n];
        const float w1 = W[(size_t)(2 * kp + 1) * 128 + n];
        const float h0 = bf16rn(w0);
        const float h1 = bf16rn(w1);
        Bhi[kp * B_STR + n] = bf16pack(h0, h1);
        Blo[kp * B_STR + n] = bf16pack(w0 - h0, w1 - h1);
    }
    for (int i = tid; i < 128; i += 256) {
        prm[i]       = b[i];
        prm[128 + i] = lns[i];
        prm[256 + i] = lnb[i];
        prm[384 + i] = W_top[i];
        prm[512 + i] = W_top[128 + i];
    }

    const int roffL = (w >> 1) * 16;
    const int noff  = (w & 1) * 64;

    for (int r0 = blockIdx.x * 64; r0 < rows; r0 += gridDim.x * 64) {
        __syncthreads();
        const int nrows = min(64, rows - r0);

        // ---- stage + aggregate: warp owns nodes w*8 .. w*8+7 ----
        for (int q = 0; q < 8; q++) {
            const int rl = w * 8 + q;
            float4 nh4 = make_float4(0.f, 0.f, 0.f, 0.f);
            float4 acc = make_float4(0.f, 0.f, 0.f, 0.f);
            if (rl < nrows) {
                const int node = r0 + rl;
                nh4 = ((const float4*)nh_old)[(size_t)node * HV4 + lane];
                acc = ((const float4*)agg_base)[(size_t)node * HV4 + lane];
                const float sdy = sdot_cur[node].y;
                const int beg = off[node], end = off[node + 1];
                for (int jb = beg; jb < end; jb += 32) {
                    const int j = jb + lane;
                    float wgt = 0.f;
                    int   sj  = 0;
                    if (j < end) {
                        sj = src_csr[j];
                        const float p = sdot_cur[sj].x + sdy + edot_csr[j];
                        wgt = 1.f / (1.f + __expf(-p));
                        if (LAST) ew[eid_csr[j]] = wgt;
                    }
                    const int m = min(32, end - jb);
                    float4 a1 = make_float4(0.f, 0.f, 0.f, 0.f);
                    float4 a2 = a1, a3 = a1;
                    int jj = 0;
                    for (; jj + 4 <= m; jj += 4) {
                        const int s0 = __shfl_sync(0xffffffffu, sj, jj);
                        const int s1 = __shfl_sync(0xffffffffu, sj, jj + 1);
                        const int s2 = __shfl_sync(0xffffffffu, sj, jj + 2);
                        const int s3 = __shfl_sync(0xffffffffu, sj, jj + 3);
                        const float w0 = __shfl_sync(0xffffffffu, wgt, jj);
                        const float w1 = __shfl_sync(0xffffffffu, wgt, jj + 1);
                        const float w2 = __shfl_sync(0xffffffffu, wgt, jj + 2);
                        const float w3 = __shfl_sync(0xffffffffu, wgt, jj + 3);
                        const float4 f0 = ((const float4*)nh_old)[(size_t)s0 * HV4 + lane];
                        const float4 f1 = ((const float4*)nh_old)[(size_t)s1 * HV4 + lane];
                        const float4 f2 = ((const float4*)nh_old)[(size_t)s2 * HV4 + lane];
                        const float4 f3 = ((const float4*)nh_old)[(size_t)s3 * HV4 + lane];
                        fma4(acc, f0, w0);
                        fma4(a1, f1, w1);
                        fma4(a2, f2, w2);
                        fma4(a3, f3, w3);
                    }
                    for (; jj < m; jj++) {
                        const int s0 = __shfl_sync(0xffffffffu, sj, jj);
                        const float w0 = __shfl_sync(0xffffffffu, wgt, jj);
                        const float4 f0 = ((const float4*)nh_old)[(size_t)s0 * HV4 + lane];
                        fma4(acc, f0, w0);
                    }
                    acc.x += a1.x + a2.x + a3.x;
                    acc.y += a1.y + a2.y + a3.y;
                    acc.z += a1.z + a2.z + a3.z;
                    acc.w += a1.w + a2.w + a3.w;
                }
            }
            // store hi/lo bf16 planes: nh4 -> kp 2*lane(+1); acc -> kp 64+2*lane(+1)
            const float hx = bf16rn(nh4.x), hy = bf16rn(nh4.y);
            const float hz = bf16rn(nh4.z), hw = bf16rn(nh4.w);
            Ahi[(2 * lane) * A_STR + rl]     = bf16pack(hx, hy);
            Ahi[(2 * lane + 1) * A_STR + rl] = bf16pack(hz, hw);
            Alo[(2 * lane) * A_STR + rl]     = bf16pack(nh4.x - hx, nh4.y - hy);
            Alo[(2 * lane + 1) * A_STR + rl] = bf16pack(nh4.z - hz, nh4.w - hw);
            const float ax = bf16rn(acc.x), ay = bf16rn(acc.y);
            const float az = bf16rn(acc.z), aw = bf16rn(acc.w);
            Ahi[(64 + 2 * lane) * A_STR + rl] = bf16pack(ax, ay);
            Ahi[(65 + 2 * lane) * A_STR + rl] = bf16pack(az, aw);
            Alo[(64 + 2 * lane) * A_STR + rl] = bf16pack(acc.x - ax, acc.y - ay);
            Alo[(65 + 2 * lane) * A_STR + rl] = bf16pack(acc.z - az, acc.w - aw);
        }
        __syncthreads();

        // ---- MMA mainloop ----
        float c[8][4];
        #pragma unroll
        for (int nt = 0; nt < 8; nt++)
            c[nt][0] = c[nt][1] = c[nt][2] = c[nt][3] = 0.f;

        #pragma unroll 2
        for (int k = 0; k < 16; k++) {
            const int kp0 = 8 * k + t4;
            const uint32_t ah0 = Ahi[kp0 * A_STR + roffL + g];
            const uint32_t ah1 = Ahi[kp0 * A_STR + roffL + g + 8];
            const uint32_t ah2 = Ahi[(kp0 + 4) * A_STR + roffL + g];
            const uint32_t ah3 = Ahi[(kp0 + 4) * A_STR + roffL + g + 8];
            const uint32_t al0 = Alo[kp0 * A_STR + roffL + g];
            const uint32_t al1 = Alo[kp0 * A_STR + roffL + g + 8];
            const uint32_t al2 = Alo[(kp0 + 4) * A_STR + roffL + g];
            const uint32_t al3 = Alo[(kp0 + 4) * A_STR + roffL + g + 8];
            const uint32_t* B0h = Bhi + kp0 * B_STR + noff + g;
            const uint32_t* B1h = Bhi + (kp0 + 4) * B_STR + noff + g;
            const uint32_t* B0l = Blo + kp0 * B_STR + noff + g;
            const uint32_t* B1l = Blo + (kp0 + 4) * B_STR + noff + g;
            #pragma unroll
            for (int nt = 0; nt < 8; nt++) {
                const uint32_t bh0 = B0h[nt * 8];
                const uint32_t bh1 = B1h[nt * 8];
                const uint32_t bl0 = B0l[nt * 8];
                const uint32_t bl1 = B1l[nt * 8];
                mma16816(c[nt], ah0, ah1, ah2, ah3, bh0, bh1);
                mma16816(c[nt], ah0, ah1, ah2, ah3, bl0, bl1);
                mma16816(c[nt], al0, al1, al2, al3, bh0, bh1);
            }
        }

        // ---- epilogue: residual + bias, LN, ReLU, sdot (reads row-clamped) ----
        const int lr0 = roffL + g;
        const int lr1 = roffL + g + 8;
        const size_t gr0 = (size_t)r0 + min(lr0, nrows - 1);
        const size_t gr1 = (size_t)r0 + min(lr1, nrows - 1);
        const int colh0 = (w & 1) * 32 + t4;

        float2 v0[8], v1[8];
        float s0 = 0.f, ss0 = 0.f, s1r = 0.f, ss1r = 0.f;
        #pragma unroll
        for (int nt = 0; nt < 8; nt++) {
            const int ch = colh0 + nt * 4;
            const float2 res0 = nh2[gr0 * 64 + ch];
            const float2 res1 = nh2[gr1 * 64 + ch];
            const float2 bia  = prm2[ch];
            float2 a0v, a1v;
            a0v.x = c[nt][0] + res0.x + bia.x;
            a0v.y = c[nt][1] + res0.y + bia.y;
            a1v.x = c[nt][2] + res1.x + bia.x;
            a1v.y = c[nt][3] + res1.y + bia.y;
            v0[nt] = a0v;
            v1[nt] = a1v;
            s0  += a0v.x + a0v.y;  ss0  += a0v.x * a0v.x + a0v.y * a0v.y;
            s1r += a1v.x + a1v.y;  ss1r += a1v.x * a1v.x + a1v.y * a1v.y;
        }
        #pragma unroll
        for (int off_ = 1; off_ <= 2; off_ <<= 1) {
            s0   += __shfl_xor_sync(0xffffffffu, s0, off_);
            ss0  += __shfl_xor_sync(0xffffffffu, ss0, off_);
            s1r  += __shfl_xor_sync(0xffffffffu, s1r, off_);
            ss1r += __shfl_xor_sync(0xffffffffu, ss1r, off_);
        }
        if (t4 == 0) {
            red[lr0 * 2 + (w & 1)] = make_float2(s0, ss0);
            red[lr1 * 2 + (w & 1)] = make_float2(s1r, ss1r);
        }
        __syncthreads();

        const float2 pa = red[lr0 * 2 + 0], pb = red[lr0 * 2 + 1];
        const float2 qa = red[lr1 * 2 + 0], qb = red[lr1 * 2 + 1];
        const float mean0 = (pa.x + pb.x) * (1.f / 128.f);
        const float var0  = (pa.y + pb.y) * (1.f / 128.f) - mean0 * mean0;
        const float rstd0 = rsqrtf(var0 + 1e-6f);
        const float mean1 = (qa.x + qb.x) * (1.f / 128.f);
        const float var1  = (qa.y + qb.y) * (1.f / 128.f) - mean1 * mean1;
        const float rstd1 = rsqrtf(var1 + 1e-6f);

        float d0s = 0.f, d0d = 0.f, d1s = 0.f, d1d = 0.f;
        #pragma unroll
        for (int nt = 0; nt < 8; nt++) {
            const int ch = colh0 + nt * 4;
            const float2 sc2 = prm2[64 + ch];
            const float2 bi2 = prm2[128 + ch];
            float2 o0, o1;
            o0.x = fmaxf((v0[nt].x - mean0) * rstd0 * sc2.x + bi2.x, 0.f);
            o0.y = fmaxf((v0[nt].y - mean0) * rstd0 * sc2.y + bi2.y, 0.f);
            o1.x = fmaxf((v1[nt].x - mean1) * rstd1 * sc2.x + bi2.x, 0.f);
            o1.y = fmaxf((v1[nt].y - mean1) * rstd1 * sc2.y + bi2.y, 0.f);
            if (lr0 < nrows) outp2[((size_t)r0 + lr0) * 64 + ch] = o0;
            if (lr1 < nrows) outp2[((size_t)r0 + lr1) * 64 + ch] = o1;
            if (!LAST) {
                const float2 ws2 = prm2[192 + ch];
                const float2 wd2 = prm2[256 + ch];
                d0s += o0.x * ws2.x + o0.y * ws2.y;
                d0d += o0.x * wd2.x + o0.y * wd2.y;
                d1s += o1.x * ws2.x + o1.y * ws2.y;
                d1d += o1.x * wd2.x + o1.y * wd2.y;
            }
        }
        if (!LAST) {
            #pragma unroll
            for (int off_ = 1; off_ <= 2; off_ <<= 1) {
                d0s += __shfl_xor_sync(0xffffffffu, d0s, off_);
                d0d += __shfl_xor_sync(0xffffffffu, d0d, off_);
                d1s += __shfl_xor_sync(0xffffffffu, d1s, off_);
                d1d += __shfl_xor_sync(0xffffffffu, d1d, off_);
            }
            if (t4 == 0) {
                sdp[lr0 * 2 + (w & 1)] = make_float2(d0s, d0d);
                sdp[lr1 * 2 + (w & 1)] = make_float2(d1s, d1d);
            }
            __syncthreads();
            if (tid < 64 && tid < nrows) {
                const float2 a = sdp[tid * 2 + 0];
                const float2 bb = sdp[tid * 2 + 1];
                sdot_nxt[r0 + tid] = make_float2(a.x + bb.x, a.y + bb.y);
            }
        }
    }
}

extern "C" void kernel_launch(void* const* d_in, const int* in_sizes, int n_in,
                              void* d_out, int out_size)
{
    const float* node_features = (const float*)d_in[0];
    const float* edge_features = (const float*)d_in[1];
    const int*   edge_indices  = (const int*)d_in[2];
    const float* W_node   = (const float*)d_in[3];
    const float* b_node   = (const float*)d_in[4];
    const float* W_edge   = (const float*)d_in[5];
    const float* b_edge   = (const float*)d_in[6];
    const float* W_gnn    = (const float*)d_in[7];
    const float* b_gnn    = (const float*)d_in[8];
    const float* W_top    = (const float*)d_in[9];
    const float* b_top    = (const float*)d_in[10];
    const float* ln_scale = (const float*)d_in[11];
    const float* ln_bias  = (const float*)d_in[12];

    float *nh_a, *nh_b, *agg_base, *escratch, *edot, *wcombo;
    int *cnt, *offp, *cur, *src_csr, *eid_csr;
    float *edot_csr;
    cudaGetSymbolAddress((void**)&nh_a,     g_node_h);
    cudaGetSymbolAddress((void**)&nh_b,     g_node_h2);
    cudaGetSymbolAddress((void**)&agg_base, g_agg_base);
    cudaGetSymbolAddress((void**)&escratch, g_escratch);
    cudaGetSymbolAddress((void**)&edot,     g_edot);
    cudaGetSymbolAddress((void**)&wcombo,   g_wcombo);
    cudaGetSymbolAddress((void**)&cnt,      g_cnt);
    cudaGetSymbolAddress((void**)&offp,     g_off);
    cudaGetSymbolAddress((void**)&cur,      g_cur);
    cudaGetSymbolAddress((void**)&src_csr,  g_src_csr);
    cudaGetSymbolAddress((void**)&eid_csr,  g_eid_csr);
    cudaGetSymbolAddress((void**)&edot_csr, g_edot_csr);

    float* eaggF  = escratch;              // [NN,64] precompute phase
    float* deg    = escratch + NN * 64;    // [NN]
    float2* sdot_a = (float2*)escratch;            // [NN] layer phase
    float2* sdot_b = (float2*)(escratch + 2 * NN); // [NN]

    float* out_node = (float*)d_out;
    float* out_ew   = (float*)d_out + (size_t)NN * H;

    const int* srcp = edge_indices;
    const int* dstp = edge_indices + NE;

    const int smem_e128 = (128 * H + 32 * 128) * 4;
    const int smem_e64  = (64 * H + 32 * 64) * 4;
    cudaFuncSetAttribute((const void*)embed_kernel<128, false, true>,
                         cudaFuncAttributeMaxDynamicSharedMemorySize, smem_e128);
    cudaFuncSetAttribute((const void*)embed_kernel<64, true, false>,
                         cudaFuncAttributeMaxDynamicSharedMemorySize, smem_e64);
    cudaFuncSetAttribute((const void*)gnn_fused_kernel<false>,
                         cudaFuncAttributeMaxDynamicSharedMemorySize, SMEM_TC);
    cudaFuncSetAttribute((const void*)gnn_fused_kernel<true>,
                         cudaFuncAttributeMaxDynamicSharedMemorySize, SMEM_TC);

    // --- one-time precompute + CSR build ---
    combo_kernel<<<1, 64>>>(W_edge, W_top, b_edge, b_top, wcombo);
    zero_kernel<<<(NN * 65 / 4 + 255) / 256, 256>>>((float4*)escratch, NN * 65 / 4);
    zero_kernel<<<(NN / 4 + 255) / 256, 256>>>((float4*)cnt, NN / 4);
    edge_pre_kernel<<<NE / 8, 256>>>(edge_features, dstp, wcombo, eaggF, deg, cnt, edot);
    scan_kernel<<<1, 1024>>>(cnt, offp, cur);
    scatter_kernel<<<(NE + 255) / 256, 256>>>(srcp, dstp, edot, cur,
                                              src_csr, eid_csr, edot_csr);
    embed_kernel<64, true, false><<<512, 256, smem_e64>>>(
        eaggF, W_edge, b_edge, deg, nullptr, agg_base, nullptr, NN);
    embed_kernel<128, false, true><<<512, 256, smem_e128>>>(
        node_features, W_node, b_node, nullptr, W_top, nh_a, sdot_a, NN);

    // --- layers (fused: aggregation + GEMM + LN), ping-pong buffers ---
    gnn_fused_kernel<false><<<148, 256, SMEM_TC>>>(
        nh_a, nh_b, agg_base, offp, src_csr, eid_csr, edot_csr,
        sdot_a, sdot_b,
        W_gnn + (size_t)0 * 256 * H, b_gnn + 0 * H, ln_scale + 0 * H, ln_bias + 0 * H,
        W_top, nullptr, NN);
    gnn_fused_kernel<false><<<148, 256, SMEM_TC>>>(
        nh_b, nh_a, agg_base, offp, src_csr, eid_csr, edot_csr,
        sdot_b, sdot_a,
        W_gnn + (size_t)1 * 256 * H, b_gnn + 1 * H, ln_scale + 1 * H, ln_bias + 1 * H,
        W_top, nullptr, NN);
    gnn_fused_kernel<true><<<148, 256, SMEM_TC>>>(
        nh_a, out_node, agg_base, offp, src_csr, eid_csr, edot_csr,
        sdot_a, nullptr,
        W_gnn + (size_t)2 * 256 * H, b_gnn + 2 * H, ln_scale + 2 * H, ln_bias + 2 * H,
        W_top, out_ew, NN);
}

// round 11
// speedup vs baseline: 1.5260x; 1.2153x over previous
#include <cuda_runtime.h>
#include <cuda_bf16.h>
#include <cstdint>

#define NN 50000
#define NE 200000
#define H  128
#define HV4 32   // H/4

// Scratch (device globals: allocation-free per harness rules)
__device__ float g_node_h[NN * H];        // 25.6 MB  node_h buffer A
__device__ float g_node_h2[NN * H];       // 25.6 MB  node_h buffer B (ping-pong)
__device__ float g_agg_base[NN * H];      // 25.6 MB  Σ edge_h per dst (factorized)
__device__ float g_escratch[NN * 65];     // precompute: eaggF [NN,64] + deg [NN]; layers: sdot_a|sdot_b
__device__ float g_edot[NE];              // folded edge-constant gate logit
__device__ float g_wcombo[65];            // W_edge @ w_top_e (64) + folded bias
// CSR (dst-sorted edge list), built once per call
__device__ int   g_cnt[NN];
__device__ int   g_off[NN + 1];
__device__ int   g_cur[NN];
__device__ int   g_src_csr[NE];
__device__ int   g_eid_csr[NE];
__device__ float g_edot_csr[NE];

__device__ __forceinline__ void fma4(float4& acc, const float4& wv, float s) {
    acc.x += wv.x * s;
    acc.y += wv.y * s;
    acc.z += wv.z * s;
    acc.w += wv.w * s;
}
__device__ __forceinline__ void red_v2(float* p, float a, float b) {
    asm volatile("red.global.add.v2.f32 [%0], {%1,%2};"
                 :: "l"(p), "f"(a), "f"(b) : "memory");
}
__device__ __forceinline__ uint32_t bf16pack(float a, float b) {
    uint32_t r;
    asm("{.reg .b16 x, y; cvt.rn.bf16.f32 x, %1; cvt.rn.bf16.f32 y, %2; mov.b32 %0, {x, y};}"
        : "=r"(r) : "f"(a), "f"(b));
    return r;
}
__device__ __forceinline__ float bf16rn(float x) {
    return __bfloat162float(__float2bfloat16_rn(x));
}
__device__ __forceinline__ void mma16816(float* c,
                                         uint32_t a0, uint32_t a1, uint32_t a2, uint32_t a3,
                                         uint32_t b0, uint32_t b1) {
    asm("mma.sync.aligned.m16n8k16.row.col.f32.bf16.bf16.f32 "
        "{%0,%1,%2,%3}, {%4,%5,%6,%7}, {%8,%9}, {%0,%1,%2,%3};"
        : "+f"(c[0]), "+f"(c[1]), "+f"(c[2]), "+f"(c[3])
        : "r"(a0), "r"(a1), "r"(a2), "r"(a3), "r"(b0), "r"(b1));
}

__global__ void zero_kernel(float4* __restrict__ p, int n4) {
    int i = blockIdx.x * blockDim.x + threadIdx.x;
    if (i < n4) p[i] = make_float4(0.f, 0.f, 0.f, 0.f);
}

// ---------------------------------------------------------------------------
__global__ void combo_kernel(const float* __restrict__ W_edge,
                             const float* __restrict__ W_top,
                             const float* __restrict__ b_edge,
                             const float* __restrict__ b_top,
                             float* __restrict__ wcombo)
{
    const int k = threadIdx.x;   // 64 threads
    float s = 0.f;
    for (int h = 0; h < H; h++) s += W_edge[k * H + h] * W_top[2 * H + h];
    wcombo[k] = s;
    if (k == 0) {
        float b = b_top[0];
        for (int h = 0; h < H; h++) b += b_edge[h] * W_top[2 * H + h];
        wcombo[64] = b;
    }
}

// ---------------------------------------------------------------------------
__global__ void edge_pre_kernel(const float* __restrict__ ef,
                                const int* __restrict__ dst,
                                const float* __restrict__ wcombo,
                                float* __restrict__ eaggF,
                                float* __restrict__ deg,
                                int* __restrict__ cnt,
                                float* __restrict__ edot)
{
    __shared__ float wsh[65];
    const int tid  = threadIdx.x;
    const int lane = tid & 31;
    const int wid  = tid >> 5;
    if (tid < 65) wsh[tid] = wcombo[tid];
    __syncthreads();

    const int e = blockIdx.x * 8 + wid;
    const int d = dst[e];
    float2 v = ((const float2*)ef)[(size_t)e * 32 + lane];
    float p = v.x * wsh[lane * 2] + v.y * wsh[lane * 2 + 1];
    #pragma unroll
    for (int off = 16; off; off >>= 1)
        p += __shfl_xor_sync(0xffffffffu, p, off);
    if (lane == 0) {
        edot[e] = p + wsh[64];
        atomicAdd(deg + d, 1.f);
        atomicAdd(cnt + d, 1);
    }
    red_v2(eaggF + (size_t)d * 64 + lane * 2, v.x, v.y);
}

// ---------------------------------------------------------------------------
__global__ void scan_kernel(const int* __restrict__ cnt,
                            int* __restrict__ off,
                            int* __restrict__ cur)
{
    __shared__ int sums[1024];
    const int t = threadIdx.x;
    const int CH = (NN + 1023) / 1024;   // 49
    const int base = t * CH;
    int s = 0;
    for (int i = 0; i < CH; i++) {
        const int idx = base + i;
        if (idx < NN) s += cnt[idx];
    }
    sums[t] = s;
    __syncthreads();
    int x = s;
    for (int d = 1; d < 1024; d <<= 1) {
        const int y = (t >= d) ? sums[t - d] : 0;
        __syncthreads();
        x += y;
        sums[t] = x;
        __syncthreads();
    }
    int run = x - s;   // exclusive prefix
    for (int i = 0; i < CH; i++) {
        const int idx = base + i;
        if (idx < NN) {
            off[idx] = run;
            cur[idx] = run;
            run += cnt[idx];
        }
    }
    if (t == 1023) off[NN] = NE;
}

__global__ void scatter_kernel(const int* __restrict__ src,
                               const int* __restrict__ dst,
                               const float* __restrict__ edot,
                               int* __restrict__ cur,
                               int* __restrict__ src_csr,
                               int* __restrict__ eid_csr,
                               float* __restrict__ edot_csr)
{
    const int e = blockIdx.x * 256 + threadIdx.x;
    if (e >= NE) return;
    const int d = dst[e];
    const int pos = atomicAdd(cur + d, 1);
    src_csr[pos]  = src[e];
    eid_csr[pos]  = e;
    edot_csr[pos] = edot[e];
}

// ---------------------------------------------------------------------------
// Embed GEMM (R3-proven): out[rows,H] = X[rows,K] @ W[K,H] + scale*b
// ---------------------------------------------------------------------------
template<int K, bool DEGBIAS, bool SDOT>
__global__ void embed_kernel(const float* __restrict__ X,
                             const float* __restrict__ W,
                             const float* __restrict__ b,
                             const float* __restrict__ deg,
                             const float* __restrict__ W_top,
                             float* __restrict__ out,
                             float2* __restrict__ sdot2, int rows)
{
    extern __shared__ float sm[];
    float* Wsh  = sm;            // K*H floats
    float* xbuf = sm + K * H;    // 32*K floats

    const int tid  = threadIdx.x;
    const int lane = tid & 31;
    const int wid  = tid >> 5;

    for (int i = tid; i < K * H / 4; i += 256)
        ((float4*)Wsh)[i] = ((const float4*)W)[i];
    const float4 bias = ((const float4*)b)[lane];
    float4 wsA, wdA;
    if (SDOT) {
        wsA = ((const float4*)W_top)[lane];
        wdA = ((const float4*)W_top)[32 + lane];
    }

    for (int r0 = blockIdx.x * 32; r0 < rows; r0 += gridDim.x * 32) {
        __syncthreads();
        const int nrows = min(32, rows - r0);
        for (int i = tid; i < nrows * (K / 4); i += 256)
            ((float4*)xbuf)[i] = ((const float4*)(X + (size_t)r0 * K))[i];
        __syncthreads();

        const int rbase = wid * 4;
        if (rbase < nrows) {
            float4 acc0 = make_float4(0.f, 0.f, 0.f, 0.f);
            float4 acc1 = acc0, acc2 = acc0, acc3 = acc0;
            const float* xr0 = xbuf + (rbase + 0) * K;
            const float* xr1 = xbuf + (rbase + 1) * K;
            const float* xr2 = xbuf + (rbase + 2) * K;
            const float* xr3 = xbuf + (rbase + 3) * K;
            #pragma unroll 4
            for (int k = 0; k < K; k++) {
                float4 wv = ((float4*)Wsh)[k * HV4 + lane];
                fma4(acc0, wv, xr0[k]);
                fma4(acc1, wv, xr1[k]);
                fma4(acc2, wv, xr2[k]);
                fma4(acc3, wv, xr3[k]);
            }
            float4 accs[4] = {acc0, acc1, acc2, acc3};
            #pragma unroll
            for (int rr = 0; rr < 4; rr++) {
                const float scb = DEGBIAS ? deg[r0 + rbase + rr] : 1.f;
                float4 o;
                o.x = accs[rr].x + scb * bias.x;
                o.y = accs[rr].y + scb * bias.y;
                o.z = accs[rr].z + scb * bias.z;
                o.w = accs[rr].w + scb * bias.w;
                ((float4*)out)[(size_t)(r0 + rbase + rr) * HV4 + lane] = o;
                if (SDOT) {
                    float s1 = o.x * wsA.x + o.y * wsA.y + o.z * wsA.z + o.w * wsA.w;
                    float s2 = o.x * wdA.x + o.y * wdA.y + o.z * wdA.z + o.w * wdA.w;
                    #pragma unroll
                    for (int off = 16; off; off >>= 1) {
                        s1 += __shfl_xor_sync(0xffffffffu, s1, off);
                        s2 += __shfl_xor_sync(0xffffffffu, s2, off);
                    }
                    if (lane == 0) sdot2[r0 + rbase + rr] = make_float2(s1, s2);
                }
            }
        }
    }
}

// ---------------------------------------------------------------------------
// Fused GNN layer: CSR aggregation + bf16-split TC GEMM + LN/ReLU.
// 512 threads (16 warps). Aggregation: warp owns 4 nodes. MMA warp tile:
// 16 rows x 32 cols (4 n-tiles). LN combine across 4 column partials.
// ---------------------------------------------------------------------------
#define A_STR 73
#define B_STR 136
#define A_PLANE (128 * A_STR)
#define B_PLANE (128 * B_STR)
#define SMEM_TC ((2 * A_PLANE + 2 * B_PLANE + 640 + 1024 + 1024) * 4)

template<bool LAST>
__global__ void __launch_bounds__(512, 1)
gnn_fused_kernel(const float* __restrict__ nh_old,
                 float* __restrict__ nh_new,
                 const float* __restrict__ agg_base,
                 const int* __restrict__ off,
                 const int* __restrict__ src_csr,
                 const int* __restrict__ eid_csr,
                 const float* __restrict__ edot_csr,
                 const float2* __restrict__ sdot_cur,
                 float2* __restrict__ sdot_nxt,
                 const float* __restrict__ W,      // [256,128]
                 const float* __restrict__ b,
                 const float* __restrict__ lns,
                 const float* __restrict__ lnb,
                 const float* __restrict__ W_top,
                 float* __restrict__ ew, int rows)
{
    extern __shared__ uint32_t smu[];
    uint32_t* Ahi = smu;
    uint32_t* Alo = Ahi + A_PLANE;
    uint32_t* Bhi = Alo + A_PLANE;
    uint32_t* Blo = Bhi + B_PLANE;
    float*    prm = (float*)(Blo + B_PLANE);        // 640 floats: b|lns|lnb|ws|wd
    float2*   red = (float2*)(prm + 640);           // [64 rows][4 col-partials]
    float2*   sdp = red + 256;                      // [64 rows][4 col-partials]

    const int tid  = threadIdx.x;
    const int lane = tid & 31;
    const int w    = tid >> 5;
    const int t4   = lane & 3;
    const int g    = lane >> 2;

    const float2* nh2   = (const float2*)nh_old;
    float2*       outp2 = (float2*)nh_new;
    const float2* prm2  = (const float2*)prm;

    // ---- stage W (once): packed bf16x2 hi/lo planes ----
    for (int i = tid; i < 128 * 128; i += 512) {
        const int kp = i >> 7, n = i & 127;
        const float w0 = W[(size_t)(2 * kp) * 128 + n];
        const float w1 = W[(size_t)(2 * kp + 1) * 128 + n];
        const float h0 = bf16rn(w0);
        const float h1 = bf16rn(w1);
        Bhi[kp * B_STR + n] = bf16pack(h0, h1);
        Blo[kp * B_STR + n] = bf16pack(w0 - h0, w1 - h1);
    }
    for (int i = tid; i < 128; i += 512) {
        prm[i]       = b[i];
        prm[128 + i] = lns[i];
        prm[256 + i] = lnb[i];
        prm[384 + i] = W_top[i];
        prm[512 + i] = W_top[128 + i];
    }

    const int roffL = (w >> 2) * 16;     // row group: 0/16/32/48
    const int noff  = (w & 3) * 32;      // col group: 0/32/64/96
    const int cgrp  = w & 3;

    for (int r0 = blockIdx.x * 64; r0 < rows; r0 += gridDim.x * 64) {
        __syncthreads();
        const int nrows = min(64, rows - r0);

        // ---- stage + aggregate: warp owns nodes w*4 .. w*4+3 ----
        for (int q = 0; q < 4; q++) {
            const int rl = w * 4 + q;
            float4 nh4 = make_float4(0.f, 0.f, 0.f, 0.f);
            float4 acc = make_float4(0.f, 0.f, 0.f, 0.f);
            if (rl < nrows) {
                const int node = r0 + rl;
                nh4 = ((const float4*)nh_old)[(size_t)node * HV4 + lane];
                acc = ((const float4*)agg_base)[(size_t)node * HV4 + lane];
                const float sdy = sdot_cur[node].y;
                const int beg = off[node], end = off[node + 1];
                for (int jb = beg; jb < end; jb += 32) {
                    const int j = jb + lane;
                    float wgt = 0.f;
                    int   sj  = 0;
                    if (j < end) {
                        sj = src_csr[j];
                        const float p = sdot_cur[sj].x + sdy + edot_csr[j];
                        wgt = 1.f / (1.f + __expf(-p));
                        if (LAST) ew[eid_csr[j]] = wgt;
                    }
                    const int m = min(32, end - jb);
                    float4 a1 = make_float4(0.f, 0.f, 0.f, 0.f);
                    float4 a2 = a1, a3 = a1;
                    int jj = 0;
                    for (; jj + 4 <= m; jj += 4) {
                        const int s0 = __shfl_sync(0xffffffffu, sj, jj);
                        const int s1 = __shfl_sync(0xffffffffu, sj, jj + 1);
                        const int s2 = __shfl_sync(0xffffffffu, sj, jj + 2);
                        const int s3 = __shfl_sync(0xffffffffu, sj, jj + 3);
                        const float w0 = __shfl_sync(0xffffffffu, wgt, jj);
                        const float w1 = __shfl_sync(0xffffffffu, wgt, jj + 1);
                        const float w2 = __shfl_sync(0xffffffffu, wgt, jj + 2);
                        const float w3 = __shfl_sync(0xffffffffu, wgt, jj + 3);
                        const float4 f0 = ((const float4*)nh_old)[(size_t)s0 * HV4 + lane];
                        const float4 f1 = ((const float4*)nh_old)[(size_t)s1 * HV4 + lane];
                        const float4 f2 = ((const float4*)nh_old)[(size_t)s2 * HV4 + lane];
                        const float4 f3 = ((const float4*)nh_old)[(size_t)s3 * HV4 + lane];
                        fma4(acc, f0, w0);
                        fma4(a1, f1, w1);
                        fma4(a2, f2, w2);
                        fma4(a3, f3, w3);
                    }
                    for (; jj < m; jj++) {
                        const int s0 = __shfl_sync(0xffffffffu, sj, jj);
                        const float w0 = __shfl_sync(0xffffffffu, wgt, jj);
                        const float4 f0 = ((const float4*)nh_old)[(size_t)s0 * HV4 + lane];
                        fma4(acc, f0, w0);
                    }
                    acc.x += a1.x + a2.x + a3.x;
                    acc.y += a1.y + a2.y + a3.y;
                    acc.z += a1.z + a2.z + a3.z;
                    acc.w += a1.w + a2.w + a3.w;
                }
            }
            const float hx = bf16rn(nh4.x), hy = bf16rn(nh4.y);
            const float hz = bf16rn(nh4.z), hw = bf16rn(nh4.w);
            Ahi[(2 * lane) * A_STR + rl]     = bf16pack(hx, hy);
            Ahi[(2 * lane + 1) * A_STR + rl] = bf16pack(hz, hw);
            Alo[(2 * lane) * A_STR + rl]     = bf16pack(nh4.x - hx, nh4.y - hy);
            Alo[(2 * lane + 1) * A_STR + rl] = bf16pack(nh4.z - hz, nh4.w - hw);
            const float ax = bf16rn(acc.x), ay = bf16rn(acc.y);
            const float az = bf16rn(acc.z), aw = bf16rn(acc.w);
            Ahi[(64 + 2 * lane) * A_STR + rl] = bf16pack(ax, ay);
            Ahi[(65 + 2 * lane) * A_STR + rl] = bf16pack(az, aw);
            Alo[(64 + 2 * lane) * A_STR + rl] = bf16pack(acc.x - ax, acc.y - ay);
            Alo[(65 + 2 * lane) * A_STR + rl] = bf16pack(acc.z - az, acc.w - aw);
        }
        __syncthreads();

        // ---- MMA mainloop: C[4 n-tiles][4] ----
        float c[4][4];
        #pragma unroll
        for (int nt = 0; nt < 4; nt++)
            c[nt][0] = c[nt][1] = c[nt][2] = c[nt][3] = 0.f;

        #pragma unroll 2
        for (int k = 0; k < 16; k++) {
            const int kp0 = 8 * k + t4;
            const uint32_t ah0 = Ahi[kp0 * A_STR + roffL + g];
            const uint32_t ah1 = Ahi[kp0 * A_STR + roffL + g + 8];
            const uint32_t ah2 = Ahi[(kp0 + 4) * A_STR + roffL + g];
            const uint32_t ah3 = Ahi[(kp0 + 4) * A_STR + roffL + g + 8];
            const uint32_t al0 = Alo[kp0 * A_STR + roffL + g];
            const uint32_t al1 = Alo[kp0 * A_STR + roffL + g + 8];
            const uint32_t al2 = Alo[(kp0 + 4) * A_STR + roffL + g];
            const uint32_t al3 = Alo[(kp0 + 4) * A_STR + roffL + g + 8];
            const uint32_t* B0h = Bhi + kp0 * B_STR + noff + g;
            const uint32_t* B1h = Bhi + (kp0 + 4) * B_STR + noff + g;
            const uint32_t* B0l = Blo + kp0 * B_STR + noff + g;
            const uint32_t* B1l = Blo + (kp0 + 4) * B_STR + noff + g;
            #pragma unroll
            for (int nt = 0; nt < 4; nt++) {
                const uint32_t bh0 = B0h[nt * 8];
                const uint32_t bh1 = B1h[nt * 8];
                const uint32_t bl0 = B0l[nt * 8];
                const uint32_t bl1 = B1l[nt * 8];
                mma16816(c[nt], ah0, ah1, ah2, ah3, bh0, bh1);
                mma16816(c[nt], ah0, ah1, ah2, ah3, bl0, bl1);
                mma16816(c[nt], al0, al1, al2, al3, bh0, bh1);
            }
        }

        // ---- epilogue ----
        const int lr0 = roffL + g;
        const int lr1 = roffL + g + 8;
        const size_t gr0 = (size_t)r0 + min(lr0, nrows - 1);
        const size_t gr1 = (size_t)r0 + min(lr1, nrows - 1);
        const int colh0 = cgrp * 16 + t4;

        float2 v0[4], v1[4];
        float s0 = 0.f, ss0 = 0.f, s1r = 0.f, ss1r = 0.f;
        #pragma unroll
        for (int nt = 0; nt < 4; nt++) {
            const int ch = colh0 + nt * 4;
            const float2 res0 = nh2[gr0 * 64 + ch];
            const float2 res1 = nh2[gr1 * 64 + ch];
            const float2 bia  = prm2[ch];
            float2 a0v, a1v;
            a0v.x = c[nt][0] + res0.x + bia.x;
            a0v.y = c[nt][1] + res0.y + bia.y;
            a1v.x = c[nt][2] + res1.x + bia.x;
            a1v.y = c[nt][3] + res1.y + bia.y;
            v0[nt] = a0v;
            v1[nt] = a1v;
            s0  += a0v.x + a0v.y;  ss0  += a0v.x * a0v.x + a0v.y * a0v.y;
            s1r += a1v.x + a1v.y;  ss1r += a1v.x * a1v.x + a1v.y * a1v.y;
        }
        #pragma unroll
        for (int off_ = 1; off_ <= 2; off_ <<= 1) {
            s0   += __shfl_xor_sync(0xffffffffu, s0, off_);
            ss0  += __shfl_xor_sync(0xffffffffu, ss0, off_);
            s1r  += __shfl_xor_sync(0xffffffffu, s1r, off_);
            ss1r += __shfl_xor_sync(0xffffffffu, ss1r, off_);
        }
        if (t4 == 0) {
            red[lr0 * 4 + cgrp] = make_float2(s0, ss0);
            red[lr1 * 4 + cgrp] = make_float2(s1r, ss1r);
        }
        __syncthreads();

        float sum0 = 0.f, sq0 = 0.f, sum1 = 0.f, sq1 = 0.f;
        #pragma unroll
        for (int p = 0; p < 4; p++) {
            const float2 a = red[lr0 * 4 + p];
            const float2 bb = red[lr1 * 4 + p];
            sum0 += a.x;  sq0 += a.y;
            sum1 += bb.x; sq1 += bb.y;
        }
        const float mean0 = sum0 * (1.f / 128.f);
        const float var0  = sq0 * (1.f / 128.f) - mean0 * mean0;
        const float rstd0 = rsqrtf(var0 + 1e-6f);
        const float mean1 = sum1 * (1.f / 128.f);
        const float var1  = sq1 * (1.f / 128.f) - mean1 * mean1;
        const float rstd1 = rsqrtf(var1 + 1e-6f);

        float d0s = 0.f, d0d = 0.f, d1s = 0.f, d1d = 0.f;
        #pragma unroll
        for (int nt = 0; nt < 4; nt++) {
            const int ch = colh0 + nt * 4;
            const float2 sc2 = prm2[64 + ch];
            const float2 bi2 = prm2[128 + ch];
            float2 o0, o1;
            o0.x = fmaxf((v0[nt].x - mean0) * rstd0 * sc2.x + bi2.x, 0.f);
            o0.y = fmaxf((v0[nt].y - mean0) * rstd0 * sc2.y + bi2.y, 0.f);
            o1.x = fmaxf((v1[nt].x - mean1) * rstd1 * sc2.x + bi2.x, 0.f);
            o1.y = fmaxf((v1[nt].y - mean1) * rstd1 * sc2.y + bi2.y, 0.f);
            if (lr0 < nrows) outp2[((size_t)r0 + lr0) * 64 + ch] = o0;
            if (lr1 < nrows) outp2[((size_t)r0 + lr1) * 64 + ch] = o1;
            if (!LAST) {
                const float2 ws2 = prm2[192 + ch];
                const float2 wd2 = prm2[256 + ch];
                d0s += o0.x * ws2.x + o0.y * ws2.y;
                d0d += o0.x * wd2.x + o0.y * wd2.y;
                d1s += o1.x * ws2.x + o1.y * ws2.y;
                d1d += o1.x * wd2.x + o1.y * wd2.y;
            }
        }
        if (!LAST) {
            #pragma unroll
            for (int off_ = 1; off_ <= 2; off_ <<= 1) {
                d0s += __shfl_xor_sync(0xffffffffu, d0s, off_);
                d0d += __shfl_xor_sync(0xffffffffu, d0d, off_);
                d1s += __shfl_xor_sync(0xffffffffu, d1s, off_);
                d1d += __shfl_xor_sync(0xffffffffu, d1d, off_);
            }
            if (t4 == 0) {
                sdp[lr0 * 4 + cgrp] = make_float2(d0s, d0d);
                sdp[lr1 * 4 + cgrp] = make_float2(d1s, d1d);
            }
            __syncthreads();
            if (tid < 64 && tid < nrows) {
                float sx = 0.f, sy = 0.f;
                #pragma unroll
                for (int p = 0; p < 4; p++) {
                    const float2 a = sdp[tid * 4 + p];
                    sx += a.x;
                    sy += a.y;
                }
                sdot_nxt[r0 + tid] = make_float2(sx, sy);
            }
        }
    }
}

extern "C" void kernel_launch(void* const* d_in, const int* in_sizes, int n_in,
                              void* d_out, int out_size)
{
    const float* node_features = (const float*)d_in[0];
    const float* edge_features = (const float*)d_in[1];
    const int*   edge_indices  = (const int*)d_in[2];
    const float* W_node   = (const float*)d_in[3];
    const float* b_node   = (const float*)d_in[4];
    const float* W_edge   = (const float*)d_in[5];
    const float* b_edge   = (const float*)d_in[6];
    const float* W_gnn    = (const float*)d_in[7];
    const float* b_gnn    = (const float*)d_in[8];
    const float* W_top    = (const float*)d_in[9];
    const float* b_top    = (const float*)d_in[10];
    const float* ln_scale = (const float*)d_in[11];
    const float* ln_bias  = (const float*)d_in[12];

    float *nh_a, *nh_b, *agg_base, *escratch, *edot, *wcombo;
    int *cnt, *offp, *cur, *src_csr, *eid_csr;
    float *edot_csr;
    cudaGetSymbolAddress((void**)&nh_a,     g_node_h);
    cudaGetSymbolAddress((void**)&nh_b,     g_node_h2);
    cudaGetSymbolAddress((void**)&agg_base, g_agg_base);
    cudaGetSymbolAddress((void**)&escratch, g_escratch);
    cudaGetSymbolAddress((void**)&edot,     g_edot);
    cudaGetSymbolAddress((void**)&wcombo,   g_wcombo);
    cudaGetSymbolAddress((void**)&cnt,      g_cnt);
    cudaGetSymbolAddress((void**)&offp,     g_off);
    cudaGetSymbolAddress((void**)&cur,      g_cur);
    cudaGetSymbolAddress((void**)&src_csr,  g_src_csr);
    cudaGetSymbolAddress((void**)&eid_csr,  g_eid_csr);
    cudaGetSymbolAddress((void**)&edot_csr, g_edot_csr);

    float* eaggF  = escratch;              // [NN,64] precompute phase
    float* deg    = escratch + NN * 64;    // [NN]
    float2* sdot_a = (float2*)escratch;            // [NN] layer phase
    float2* sdot_b = (float2*)(escratch + 2 * NN); // [NN]

    float* out_node = (float*)d_out;
    float* out_ew   = (float*)d_out + (size_t)NN * H;

    const int* srcp = edge_indices;
    const int* dstp = edge_indices + NE;

    const int smem_e128 = (128 * H + 32 * 128) * 4;
    const int smem_e64  = (64 * H + 32 * 64) * 4;
    cudaFuncSetAttribute((const void*)embed_kernel<128, false, true>,
                         cudaFuncAttributeMaxDynamicSharedMemorySize, smem_e128);
    cudaFuncSetAttribute((const void*)embed_kernel<64, true, false>,
                         cudaFuncAttributeMaxDynamicSharedMemorySize, smem_e64);
    cudaFuncSetAttribute((const void*)gnn_fused_kernel<false>,
                         cudaFuncAttributeMaxDynamicSharedMemorySize, SMEM_TC);
    cudaFuncSetAttribute((const void*)gnn_fused_kernel<true>,
                         cudaFuncAttributeMaxDynamicSharedMemorySize, SMEM_TC);

    // --- one-time precompute + CSR build ---
    combo_kernel<<<1, 64>>>(W_edge, W_top, b_edge, b_top, wcombo);
    zero_kernel<<<(NN * 65 / 4 + 255) / 256, 256>>>((float4*)escratch, NN * 65 / 4);
    zero_kernel<<<(NN / 4 + 255) / 256, 256>>>((float4*)cnt, NN / 4);
    edge_pre_kernel<<<NE / 8, 256>>>(edge_features, dstp, wcombo, eaggF, deg, cnt, edot);
    scan_kernel<<<1, 1024>>>(cnt, offp, cur);
    scatter_kernel<<<(NE + 255) / 256, 256>>>(srcp, dstp, edot, cur,
                                              src_csr, eid_csr, edot_csr);
    embed_kernel<64, true, false><<<512, 256, smem_e64>>>(
        eaggF, W_edge, b_edge, deg, nullptr, agg_base, nullptr, NN);
    embed_kernel<128, false, true><<<512, 256, smem_e128>>>(
        node_features, W_node, b_node, nullptr, W_top, nh_a, sdot_a, NN);

    // --- layers (fused), ping-pong buffers ---
    gnn_fused_kernel<false><<<148, 512, SMEM_TC>>>(
        nh_a, nh_b, agg_base, offp, src_csr, eid_csr, edot_csr,
        sdot_a, sdot_b,
        W_gnn + (size_t)0 * 256 * H, b_gnn + 0 * H, ln_scale + 0 * H, ln_bias + 0 * H,
        W_top, nullptr, NN);
    gnn_fused_kernel<false><<<148, 512, SMEM_TC>>>(
        nh_b, nh_a, agg_base, offp, src_csr, eid_csr, edot_csr,
        sdot_b, sdot_a,
        W_gnn + (size_t)1 * 256 * H, b_gnn + 1 * H, ln_scale + 1 * H, ln_bias + 1 * H,
        W_top, nullptr, NN);
    gnn_fused_kernel<true><<<148, 512, SMEM_TC>>>(
        nh_a, out_node, agg_base, offp, src_csr, eid_csr, edot_csr,
        sdot_a, nullptr,
        W_gnn + (size_t)2 * 256 * H, b_gnn + 2 * H, ln_scale + 2 * H, ln_bias + 2 * H,
        W_top, out_ew, NN);
}